// round 1
// baseline (speedup 1.0000x reference)
#include <cuda_runtime.h>

#define BS_  2
#define SEQ  2048
#define EMB  1024
#define NH   16
#define HD   64
#define MROWS (BS_*SEQ)   // 4096

// scratch (device globals — no allocations allowed)
__device__ float g_q[BS_*SEQ*EMB];
__device__ float g_k[BS_*SEQ*EMB];
__device__ float g_v[BS_*SEQ*EMB];
__device__ float g_attn[BS_*SEQ*EMB];

// ----------------------------------------------------------------------------
// C[M,N] = A[M,K] @ W[N,K]^T + bias[N]   (both operands K-contiguous row-major)
// 128x128 tile, BK=8, 256 threads, 8x8 per-thread micro-tile
// ----------------------------------------------------------------------------
__global__ __launch_bounds__(256) void sgemm_tn_kernel(
    const float* __restrict__ A, const float* __restrict__ W,
    const float* __restrict__ bias, float* __restrict__ C,
    int M, int N, int K)
{
    const int BK = 8;
    __shared__ float As[BK][128];
    __shared__ float Bs[BK][128];

    int tid = threadIdx.x;
    int bm = blockIdx.y * 128;
    int bn = blockIdx.x * 128;
    int tx = (tid & 15) * 8;   // col offset of micro-tile
    int ty = (tid >> 4) * 8;   // row offset of micro-tile

    float acc[8][8] = {};

    int lrow = tid >> 1;          // 0..127
    int lcol = (tid & 1) * 4;     // 0 or 4

    const float* Ap = A + (long)(bm + lrow) * K + lcol;
    const float* Wp = W + (long)(bn + lrow) * K + lcol;

    for (int k0 = 0; k0 < K; k0 += BK) {
        float4 a4 = *(const float4*)(Ap + k0);
        float4 b4 = *(const float4*)(Wp + k0);
        As[lcol+0][lrow] = a4.x; As[lcol+1][lrow] = a4.y;
        As[lcol+2][lrow] = a4.z; As[lcol+3][lrow] = a4.w;
        Bs[lcol+0][lrow] = b4.x; Bs[lcol+1][lrow] = b4.y;
        Bs[lcol+2][lrow] = b4.z; Bs[lcol+3][lrow] = b4.w;
        __syncthreads();
        #pragma unroll
        for (int kk = 0; kk < BK; kk++) {
            float4 a0 = *(const float4*)&As[kk][ty];
            float4 a1 = *(const float4*)&As[kk][ty+4];
            float4 b0 = *(const float4*)&Bs[kk][tx];
            float4 b1 = *(const float4*)&Bs[kk][tx+4];
            float ar[8] = {a0.x,a0.y,a0.z,a0.w,a1.x,a1.y,a1.z,a1.w};
            float br[8] = {b0.x,b0.y,b0.z,b0.w,b1.x,b1.y,b1.z,b1.w};
            #pragma unroll
            for (int i = 0; i < 8; i++)
                #pragma unroll
                for (int j = 0; j < 8; j++)
                    acc[i][j] += ar[i] * br[j];
        }
        __syncthreads();
    }

    #pragma unroll
    for (int i = 0; i < 8; i++) {
        long row = bm + ty + i;
        #pragma unroll
        for (int j = 0; j < 8; j += 4) {
            float4 o;
            o.x = acc[i][j+0] + bias[bn+tx+j+0];
            o.y = acc[i][j+1] + bias[bn+tx+j+1];
            o.z = acc[i][j+2] + bias[bn+tx+j+2];
            o.w = acc[i][j+3] + bias[bn+tx+j+3];
            *(float4*)&C[row * N + bn + tx + j] = o;
        }
    }
}

// ----------------------------------------------------------------------------
// Attention: w = sigmoid(q·k / 8); out = softmax_k(w) @ v
// sigmoid output in [0,1] -> exp(w) in [1,e]: single-pass, no max needed.
// One query per thread (q + acc in registers), K/V tiles of 64 in smem.
// ----------------------------------------------------------------------------
__global__ __launch_bounds__(128) void attn_kernel(
    const float* __restrict__ Q, const float* __restrict__ K,
    const float* __restrict__ V, const int* __restrict__ indicator,
    float* __restrict__ O)
{
    __shared__ float4 Ks[64][16];
    __shared__ float4 Vs[64][16];

    int b = blockIdx.z;
    int h = blockIdx.y;
    int q = blockIdx.x * 128 + threadIdx.x;
    int tid = threadIdx.x;
    int ind = __ldg(indicator);

    const float* qp = Q + ((long)(b * SEQ + q)) * EMB + h * HD;
    float4 q4[16];
    #pragma unroll
    for (int i = 0; i < 16; i++) q4[i] = *(const float4*)(qp + i * 4);

    float4 acc[16];
    #pragma unroll
    for (int i = 0; i < 16; i++) acc[i] = make_float4(0.f, 0.f, 0.f, 0.f);
    float denom = 0.f;

    for (int kt = 0; kt < SEQ; kt += 64) {
        #pragma unroll
        for (int it = 0; it < 8; it++) {
            int idx = it * 128 + tid;     // 0..1023
            int row = idx >> 4;
            int c4  = idx & 15;
            long base = ((long)(b * SEQ + kt + row)) * EMB + h * HD + c4 * 4;
            Ks[row][c4] = *(const float4*)(K + base);
            Vs[row][c4] = *(const float4*)(V + base);
        }
        __syncthreads();
        #pragma unroll 4
        for (int kk = 0; kk < 64; kk++) {
            float dot = 0.f;
            #pragma unroll
            for (int i = 0; i < 16; i++) {
                float4 kv = Ks[kk][i];
                dot += q4[i].x * kv.x + q4[i].y * kv.y
                     + q4[i].z * kv.z + q4[i].w * kv.w;
            }
            float s = dot * 0.125f;                  // / sqrt(64)
            float p = 1.f / (1.f + __expf(-s));      // sigmoid
            if (ind) p = 1.f - p;
            float e = __expf(p);                     // softmax numerator (bounded)
            denom += e;
            #pragma unroll
            for (int i = 0; i < 16; i++) {
                float4 vv = Vs[kk][i];
                acc[i].x += e * vv.x; acc[i].y += e * vv.y;
                acc[i].z += e * vv.z; acc[i].w += e * vv.w;
            }
        }
        __syncthreads();
    }

    float inv = 1.f / denom;
    float* op = O + ((long)(b * SEQ + q)) * EMB + h * HD;
    #pragma unroll
    for (int i = 0; i < 16; i++) {
        float4 o;
        o.x = acc[i].x * inv; o.y = acc[i].y * inv;
        o.z = acc[i].z * inv; o.w = acc[i].w * inv;
        *(float4*)(op + i * 4) = o;
    }
}

// ----------------------------------------------------------------------------
extern "C" void kernel_launch(void* const* d_in, const int* in_sizes, int n_in,
                              void* d_out, int out_size)
{
    const float* queries = (const float*)d_in[0];
    const float* keys    = (const float*)d_in[1];
    const float* values  = (const float*)d_in[2];
    const float* Wq = (const float*)d_in[3];
    const float* bq = (const float*)d_in[4];
    const float* Wk = (const float*)d_in[5];
    const float* bk = (const float*)d_in[6];
    const float* Wv = (const float*)d_in[7];
    const float* bv = (const float*)d_in[8];
    const float* Wo = (const float*)d_in[9];
    const float* bo = (const float*)d_in[10];
    const int* indicator = (const int*)d_in[11];

    float *gq, *gk, *gv, *ga;
    cudaGetSymbolAddress((void**)&gq, g_q);
    cudaGetSymbolAddress((void**)&gk, g_k);
    cudaGetSymbolAddress((void**)&gv, g_v);
    cudaGetSymbolAddress((void**)&ga, g_attn);

    dim3 gemm_grid(EMB / 128, MROWS / 128);   // (8, 32)
    sgemm_tn_kernel<<<gemm_grid, 256>>>(queries, Wq, bq, gq, MROWS, EMB, EMB);
    sgemm_tn_kernel<<<gemm_grid, 256>>>(keys,    Wk, bk, gk, MROWS, EMB, EMB);
    sgemm_tn_kernel<<<gemm_grid, 256>>>(values,  Wv, bv, gv, MROWS, EMB, EMB);

    dim3 attn_grid(SEQ / 128, NH, BS_);       // (16, 16, 2)
    attn_kernel<<<attn_grid, 128>>>(gq, gk, gv, indicator, ga);

    sgemm_tn_kernel<<<gemm_grid, 256>>>(ga, Wo, bo, (float*)d_out, MROWS, EMB, EMB);
}

// round 3
// speedup vs baseline: 1.0720x; 1.0720x over previous
#include <cuda_runtime.h>
#include <cstdint>

#define BS_  2
#define SEQ  2048
#define EMB  1024
#define NH   16
#define HD   64
#define MROWS (BS_*SEQ)   // 4096

// scratch (device globals — no allocations allowed)
__device__ float g_q[BS_*SEQ*EMB];
__device__ float g_k[BS_*SEQ*EMB];
__device__ float g_v[BS_*SEQ*EMB];
__device__ float g_attn[BS_*SEQ*EMB];

__device__ __forceinline__ uint32_t f2tf32(float x) {
    uint32_t r; asm("cvt.rna.tf32.f32 %0, %1;" : "=r"(r) : "f"(x)); return r;
}

__device__ __forceinline__ void mma16n8k8(float c[4], const uint32_t a[4],
                                          const uint32_t b[2]) {
    asm volatile(
        "mma.sync.aligned.m16n8k8.row.col.f32.tf32.tf32.f32 "
        "{%0,%1,%2,%3}, {%4,%5,%6,%7}, {%8,%9}, {%0,%1,%2,%3};"
        : "+f"(c[0]), "+f"(c[1]), "+f"(c[2]), "+f"(c[3])
        : "r"(a[0]), "r"(a[1]), "r"(a[2]), "r"(a[3]), "r"(b[0]), "r"(b[1]));
}

// ============================================================================
// C[M,N] = tf32(A[M,K]) @ tf32(W[N,K])^T + bias   via mma.sync (HMMA tf32)
// CTA tile 256x128, warp tile 64x64 (warps 4m x 2n), BK=32, double-buffered.
// ============================================================================
#define BM 256
#define BN 128
#define BKC 32
#define PAD 36              // row stride in words (conflict-free frag loads)
#define OFF_A0 0
#define OFF_B0 (BM*PAD)                   // 9216
#define OFF_A1 (OFF_B0 + BN*PAD)          // 13824
#define OFF_B1 (OFF_A1 + BM*PAD)          // 23040
#define SM_WORDS (OFF_B1 + BN*PAD)        // 27648 words = 110592 B
#define NCHUNK (EMB / BKC)                // 32

__global__ void __launch_bounds__(256, 1) gemm_tf32_mma(
    const float* __restrict__ A, const float* __restrict__ W,
    const float* __restrict__ bias, float* __restrict__ C)
{
    extern __shared__ uint32_t sm[];

    const int tid  = threadIdx.x;
    const int lane = tid & 31;
    const int wid  = tid >> 5;
    const int wm   = wid >> 1;     // 0..3
    const int wn   = wid & 1;      // 0..1
    const int bm   = blockIdx.y * BM;
    const int bn   = blockIdx.x * BN;

    // gmem load mapping: A: 2048 float4 / 256 thr = 8 each; B: 1024/256 = 4
    // A f4 id = tid + i*256 -> m=id>>3, c=id&7 ; B likewise over 128 rows
    float4 ra[8], rb[4];

    const float* Ap = A + (long)bm * EMB;
    const float* Wp = W + (long)bn * EMB;

    auto ldgA = [&](int c) {
        int k0 = c * BKC;
        #pragma unroll
        for (int i = 0; i < 8; i++) {
            int id = tid + i * 256;
            ra[i] = __ldg((const float4*)(Ap + (long)(id >> 3) * EMB + k0 + (id & 7) * 4));
        }
        #pragma unroll
        for (int i = 0; i < 4; i++) {
            int id = tid + i * 256;
            rb[i] = __ldg((const float4*)(Wp + (long)(id >> 3) * EMB + k0 + (id & 7) * 4));
        }
    };
    auto stsAll = [&](int buf) {
        uint32_t* sA = sm + (buf ? OFF_A1 : OFF_A0);
        uint32_t* sB = sm + (buf ? OFF_B1 : OFF_B0);
        #pragma unroll
        for (int i = 0; i < 8; i++) {
            int id = tid + i * 256;
            uint32_t* p = sA + (id >> 3) * PAD + (id & 7) * 4;
            p[0] = f2tf32(ra[i].x); p[1] = f2tf32(ra[i].y);
            p[2] = f2tf32(ra[i].z); p[3] = f2tf32(ra[i].w);
        }
        #pragma unroll
        for (int i = 0; i < 4; i++) {
            int id = tid + i * 256;
            uint32_t* p = sB + (id >> 3) * PAD + (id & 7) * 4;
            p[0] = f2tf32(rb[i].x); p[1] = f2tf32(rb[i].y);
            p[2] = f2tf32(rb[i].z); p[3] = f2tf32(rb[i].w);
        }
    };

    float acc[4][8][4];
    #pragma unroll
    for (int mt = 0; mt < 4; mt++)
        #pragma unroll
        for (int nt = 0; nt < 8; nt++)
            #pragma unroll
            for (int j = 0; j < 4; j++) acc[mt][nt][j] = 0.f;

    ldgA(0);
    stsAll(0);
    __syncthreads();

    const int arow = wm * 64 + (lane >> 2);
    const int brow = wn * 64 + (lane >> 2);
    const int kcol = lane & 3;

    for (int c = 0; c < NCHUNK; c++) {
        if (c + 1 < NCHUNK) ldgA(c + 1);

        const uint32_t* sA = sm + ((c & 1) ? OFF_A1 : OFF_A0);
        const uint32_t* sB = sm + ((c & 1) ? OFF_B1 : OFF_B0);

        #pragma unroll
        for (int ks = 0; ks < 4; ks++) {
            int kb = ks * 8 + kcol;
            uint32_t af[4][4], bf[8][2];
            #pragma unroll
            for (int mt = 0; mt < 4; mt++) {
                const uint32_t* p = sA + (arow + mt * 16) * PAD + kb;
                af[mt][0] = p[0];
                af[mt][1] = p[8 * PAD];
                af[mt][2] = p[4];
                af[mt][3] = p[8 * PAD + 4];
            }
            #pragma unroll
            for (int nt = 0; nt < 8; nt++) {
                const uint32_t* p = sB + (brow + nt * 8) * PAD + kb;
                bf[nt][0] = p[0];
                bf[nt][1] = p[4];
            }
            #pragma unroll
            for (int mt = 0; mt < 4; mt++)
                #pragma unroll
                for (int nt = 0; nt < 8; nt++)
                    mma16n8k8(acc[mt][nt], af[mt], bf[nt]);
        }
        __syncthreads();
        if (c + 1 < NCHUNK) {
            stsAll((c + 1) & 1);
            __syncthreads();
        }
    }

    // epilogue
    #pragma unroll
    for (int mt = 0; mt < 4; mt++) {
        int r0 = bm + wm * 64 + mt * 16 + (lane >> 2);
        #pragma unroll
        for (int nt = 0; nt < 8; nt++) {
            int col = bn + wn * 64 + nt * 8 + (lane & 3) * 2;
            float2 bb = *(const float2*)(bias + col);
            float2 o0, o1;
            o0.x = acc[mt][nt][0] + bb.x; o0.y = acc[mt][nt][1] + bb.y;
            o1.x = acc[mt][nt][2] + bb.x; o1.y = acc[mt][nt][3] + bb.y;
            *(float2*)(C + (long)r0 * EMB + col) = o0;
            *(float2*)(C + (long)(r0 + 8) * EMB + col) = o1;
        }
    }
}

// ----------------------------------------------------------------------------
// Attention: w = sigmoid(q·k / 8); out = softmax_k(w) @ v
// sigmoid in [0,1] -> exp in [1,e]: single streaming pass, no running max.
// 2 threads per query (32 dims each), shfl_xor(1) combines the dot product.
// ----------------------------------------------------------------------------
__global__ __launch_bounds__(128) void attn_kernel(
    const float* __restrict__ Q, const float* __restrict__ K,
    const float* __restrict__ V, const int* __restrict__ indicator,
    float* __restrict__ O)
{
    __shared__ float4 Ks[64][16];
    __shared__ float4 Vs[64][16];

    int b = blockIdx.z;
    int h = blockIdx.y;
    int tid = threadIdx.x;
    int qi = blockIdx.x * 64 + (tid >> 1);
    int half = tid & 1;
    int ind = __ldg(indicator);

    const float* qp = Q + ((long)(b * SEQ + qi)) * EMB + h * HD + half * 32;
    float4 q4[8];
    #pragma unroll
    for (int i = 0; i < 8; i++) q4[i] = *(const float4*)(qp + i * 4);

    float4 acc[8];
    #pragma unroll
    for (int i = 0; i < 8; i++) acc[i] = make_float4(0.f, 0.f, 0.f, 0.f);
    float denom = 0.f;

    for (int kt = 0; kt < SEQ; kt += 64) {
        #pragma unroll
        for (int it = 0; it < 8; it++) {
            int idx = it * 128 + tid;     // 0..1023
            int row = idx >> 4;
            int c4  = idx & 15;
            long base = ((long)(b * SEQ + kt + row)) * EMB + h * HD + c4 * 4;
            Ks[row][c4] = *(const float4*)(K + base);
            Vs[row][c4] = *(const float4*)(V + base);
        }
        __syncthreads();
        #pragma unroll 4
        for (int kk = 0; kk < 64; kk++) {
            float dot = 0.f;
            #pragma unroll
            for (int i = 0; i < 8; i++) {
                float4 kv = Ks[kk][half * 8 + i];
                dot += q4[i].x * kv.x + q4[i].y * kv.y
                     + q4[i].z * kv.z + q4[i].w * kv.w;
            }
            dot += __shfl_xor_sync(0xffffffffu, dot, 1);
            float s = dot * 0.125f;                  // / sqrt(64)
            float p = 1.f / (1.f + __expf(-s));      // sigmoid
            if (ind) p = 1.f - p;
            float e = __expf(p);                     // bounded softmax numerator
            denom += e;
            #pragma unroll
            for (int i = 0; i < 8; i++) {
                float4 vv = Vs[kk][half * 8 + i];
                acc[i].x += e * vv.x; acc[i].y += e * vv.y;
                acc[i].z += e * vv.z; acc[i].w += e * vv.w;
            }
        }
        __syncthreads();
    }

    float inv = 1.f / denom;
    float* op = O + ((long)(b * SEQ + qi)) * EMB + h * HD + half * 32;
    #pragma unroll
    for (int i = 0; i < 8; i++) {
        float4 o;
        o.x = acc[i].x * inv; o.y = acc[i].y * inv;
        o.z = acc[i].z * inv; o.w = acc[i].w * inv;
        *(float4*)(op + i * 4) = o;
    }
}

// ----------------------------------------------------------------------------
extern "C" void kernel_launch(void* const* d_in, const int* in_sizes, int n_in,
                              void* d_out, int out_size)
{
    const float* queries = (const float*)d_in[0];
    const float* keys    = (const float*)d_in[1];
    const float* values  = (const float*)d_in[2];
    const float* Wq = (const float*)d_in[3];
    const float* bq = (const float*)d_in[4];
    const float* Wk = (const float*)d_in[5];
    const float* bk = (const float*)d_in[6];
    const float* Wv = (const float*)d_in[7];
    const float* bv = (const float*)d_in[8];
    const float* Wo = (const float*)d_in[9];
    const float* bo = (const float*)d_in[10];
    const int* indicator = (const int*)d_in[11];

    float *gq, *gk, *gv, *ga;
    cudaGetSymbolAddress((void**)&gq, g_q);
    cudaGetSymbolAddress((void**)&gk, g_k);
    cudaGetSymbolAddress((void**)&gv, g_v);
    cudaGetSymbolAddress((void**)&ga, g_attn);

    static int smem_set = 0;
    if (!smem_set) {
        cudaFuncSetAttribute(gemm_tf32_mma,
                             cudaFuncAttributeMaxDynamicSharedMemorySize,
                             SM_WORDS * 4);
        smem_set = 1;
    }

    dim3 gemm_grid(EMB / BN, MROWS / BM);   // (8, 16)
    gemm_tf32_mma<<<gemm_grid, 256, SM_WORDS * 4>>>(queries, Wq, bq, gq);
    gemm_tf32_mma<<<gemm_grid, 256, SM_WORDS * 4>>>(keys,    Wk, bk, gk);
    gemm_tf32_mma<<<gemm_grid, 256, SM_WORDS * 4>>>(values,  Wv, bv, gv);

    dim3 attn_grid(SEQ / 64, NH, BS_);      // (32, 16, 2)
    attn_kernel<<<attn_grid, 128>>>(gq, gk, gv, indicator, ga);

    gemm_tf32_mma<<<gemm_grid, 256, SM_WORDS * 4>>>(ga, Wo, bo, (float*)d_out);
}

// round 5
// speedup vs baseline: 3.4863x; 3.2520x over previous
#include <cuda_runtime.h>
#include <cstdint>

#define BS_  2
#define SEQ  2048
#define EMB  1024
#define NH   16
#define HD   64
#define MROWS (BS_*SEQ)   // 4096

__device__ float g_q[BS_*SEQ*EMB];
__device__ float g_k[BS_*SEQ*EMB];
__device__ float g_v[BS_*SEQ*EMB];
__device__ float g_attn[BS_*SEQ*EMB];

__device__ __forceinline__ uint32_t f2tf32(float x) {
    uint32_t r; asm("cvt.rna.tf32.f32 %0, %1;" : "=r"(r) : "f"(x)); return r;
}
__device__ __forceinline__ float tanh_fast(float x) {
    float r; asm("tanh.approx.f32 %0, %1;" : "=f"(r) : "f"(x)); return r;
}
__device__ __forceinline__ void mma16n8k8(float c[4], const uint32_t a[4],
                                          const uint32_t b0, const uint32_t b1) {
    asm volatile(
        "mma.sync.aligned.m16n8k8.row.col.f32.tf32.tf32.f32 "
        "{%0,%1,%2,%3}, {%4,%5,%6,%7}, {%8,%9}, {%0,%1,%2,%3};"
        : "+f"(c[0]), "+f"(c[1]), "+f"(c[2]), "+f"(c[3])
        : "r"(a[0]), "r"(a[1]), "r"(a[2]), "r"(a[3]), "r"(b0), "r"(b1));
}

// ============================================================================
// Projection GEMM: C = tf32(A) @ tf32(W)^T + bias  (mma.sync HMMA tf32)
// CTA 256x128, warp 64x64, BK=32, double buffered.  z selects one of up to
// 3 independent (A,W,bias,C) problems (QKV fusion).
// ============================================================================
#define BM 256
#define BN 128
#define BKC 32
#define PAD 36
#define OFF_A0 0
#define OFF_B0 (BM*PAD)
#define OFF_A1 (OFF_B0 + BN*PAD)
#define OFF_B1 (OFF_A1 + BM*PAD)
#define SM_WORDS (OFF_B1 + BN*PAD)
#define NCHUNK (EMB / BKC)

__global__ void __launch_bounds__(256, 1) gemm_tf32_mma(
    const float* __restrict__ A0, const float* __restrict__ W0, const float* __restrict__ b0_, float* __restrict__ C0,
    const float* __restrict__ A1, const float* __restrict__ W1, const float* __restrict__ b1_, float* __restrict__ C1,
    const float* __restrict__ A2, const float* __restrict__ W2, const float* __restrict__ b2_, float* __restrict__ C2)
{
    extern __shared__ uint32_t sm[];

    const float* A    = blockIdx.z == 0 ? A0 : (blockIdx.z == 1 ? A1 : A2);
    const float* W    = blockIdx.z == 0 ? W0 : (blockIdx.z == 1 ? W1 : W2);
    const float* bias = blockIdx.z == 0 ? b0_ : (blockIdx.z == 1 ? b1_ : b2_);
    float*       C    = blockIdx.z == 0 ? C0 : (blockIdx.z == 1 ? C1 : C2);

    const int tid  = threadIdx.x;
    const int lane = tid & 31;
    const int wid  = tid >> 5;
    const int wm   = wid >> 1;
    const int wn   = wid & 1;
    const int bm   = blockIdx.y * BM;
    const int bn   = blockIdx.x * BN;

    float4 ra[8], rb[4];
    const float* Ap = A + (long)bm * EMB;
    const float* Wp = W + (long)bn * EMB;

    auto ldgA = [&](int c) {
        int k0 = c * BKC;
        #pragma unroll
        for (int i = 0; i < 8; i++) {
            int id = tid + i * 256;
            ra[i] = __ldg((const float4*)(Ap + (long)(id >> 3) * EMB + k0 + (id & 7) * 4));
        }
        #pragma unroll
        for (int i = 0; i < 4; i++) {
            int id = tid + i * 256;
            rb[i] = __ldg((const float4*)(Wp + (long)(id >> 3) * EMB + k0 + (id & 7) * 4));
        }
    };
    auto stsAll = [&](int buf) {
        uint32_t* sA = sm + (buf ? OFF_A1 : OFF_A0);
        uint32_t* sB = sm + (buf ? OFF_B1 : OFF_B0);
        #pragma unroll
        for (int i = 0; i < 8; i++) {
            int id = tid + i * 256;
            uint32_t* p = sA + (id >> 3) * PAD + (id & 7) * 4;
            p[0] = f2tf32(ra[i].x); p[1] = f2tf32(ra[i].y);
            p[2] = f2tf32(ra[i].z); p[3] = f2tf32(ra[i].w);
        }
        #pragma unroll
        for (int i = 0; i < 4; i++) {
            int id = tid + i * 256;
            uint32_t* p = sB + (id >> 3) * PAD + (id & 7) * 4;
            p[0] = f2tf32(rb[i].x); p[1] = f2tf32(rb[i].y);
            p[2] = f2tf32(rb[i].z); p[3] = f2tf32(rb[i].w);
        }
    };

    float acc[4][8][4];
    #pragma unroll
    for (int mt = 0; mt < 4; mt++)
        #pragma unroll
        for (int nt = 0; nt < 8; nt++)
            #pragma unroll
            for (int j = 0; j < 4; j++) acc[mt][nt][j] = 0.f;

    ldgA(0);
    stsAll(0);
    __syncthreads();

    const int arow = wm * 64 + (lane >> 2);
    const int brow = wn * 64 + (lane >> 2);
    const int kcol = lane & 3;

    for (int c = 0; c < NCHUNK; c++) {
        if (c + 1 < NCHUNK) ldgA(c + 1);

        const uint32_t* sA = sm + ((c & 1) ? OFF_A1 : OFF_A0);
        const uint32_t* sB = sm + ((c & 1) ? OFF_B1 : OFF_B0);

        #pragma unroll
        for (int ks = 0; ks < 4; ks++) {
            int kb = ks * 8 + kcol;
            uint32_t af[4][4], bf[8][2];
            #pragma unroll
            for (int mt = 0; mt < 4; mt++) {
                const uint32_t* p = sA + (arow + mt * 16) * PAD + kb;
                af[mt][0] = p[0];
                af[mt][1] = p[8 * PAD];
                af[mt][2] = p[4];
                af[mt][3] = p[8 * PAD + 4];
            }
            #pragma unroll
            for (int nt = 0; nt < 8; nt++) {
                const uint32_t* p = sB + (brow + nt * 8) * PAD + kb;
                bf[nt][0] = p[0];
                bf[nt][1] = p[4];
            }
            #pragma unroll
            for (int mt = 0; mt < 4; mt++)
                #pragma unroll
                for (int nt = 0; nt < 8; nt++)
                    mma16n8k8(acc[mt][nt], af[mt], bf[nt][0], bf[nt][1]);
        }
        __syncthreads();
        if (c + 1 < NCHUNK) {
            stsAll((c + 1) & 1);
            __syncthreads();
        }
    }

    #pragma unroll
    for (int mt = 0; mt < 4; mt++) {
        int r0 = bm + wm * 64 + mt * 16 + (lane >> 2);
        #pragma unroll
        for (int nt = 0; nt < 8; nt++) {
            int col = bn + wn * 64 + nt * 8 + (lane & 3) * 2;
            float2 bb = *(const float2*)(bias + col);
            float2 o0, o1;
            o0.x = acc[mt][nt][0] + bb.x; o0.y = acc[mt][nt][1] + bb.y;
            o1.x = acc[mt][nt][2] + bb.x; o1.y = acc[mt][nt][3] + bb.y;
            *(float2*)(C + (long)r0 * EMB + col) = o0;
            *(float2*)(C + (long)(r0 + 8) * EMB + col) = o1;
        }
    }
}

// ============================================================================
// Attention via mma.sync tf32.
// w = sigmoid(qk/8) in [0,1] -> exp(w) in [1,e]: single pass, no running max.
// CTA: 128 queries x one (b,h); 8 warps x 16 rows; 64-key tiles.
// ============================================================================
#define AST 68
#define AOFF_K 0
#define AOFF_V (64*AST)
#define AOFF_P (2*64*AST)
#define A_SMEM_WORDS (AOFF_P + 128*AST)   // 17408 words = 69632 B

__global__ void __launch_bounds__(256) attn_mma(
    const float* __restrict__ Q, const float* __restrict__ K,
    const float* __restrict__ V, const int* __restrict__ indicator,
    float* __restrict__ O)
{
    extern __shared__ uint32_t sm[];
    const int tid  = threadIdx.x;
    const int lane = tid & 31;
    const int wid  = tid >> 5;             // 0..7
    const int b    = blockIdx.z;
    const int h    = blockIdx.y;
    const int q0   = blockIdx.x * 128;
    const int r    = lane >> 2;            // 0..7
    const int qq   = lane & 3;             // 0..3

    const float psign = __ldg(indicator) ? -0.5f : 0.5f;

    // ---- stage FULL Q tile [128 rows][64 dims] = 2048 float4 (fix: was half)
    {
        uint32_t* Qs = sm + AOFF_P;
        #pragma unroll
        for (int i = 0; i < 8; i++) {
            int idx = tid + i * 256;          // 0..2047
            int rr = idx >> 4, cc = idx & 15; // 128 rows x 16 float4
            float4 v = __ldg((const float4*)(Q + ((long)(b * SEQ + q0 + rr)) * EMB + h * HD + cc * 4));
            uint32_t* p = Qs + rr * AST + cc * 4;
            p[0] = f2tf32(v.x); p[1] = f2tf32(v.y); p[2] = f2tf32(v.z); p[3] = f2tf32(v.w);
        }
    }
    __syncthreads();

    uint32_t qf[8][4];
    {
        const uint32_t* Qs = sm + AOFF_P + (wid * 16 + r) * AST;
        #pragma unroll
        for (int ks = 0; ks < 8; ks++) {
            const uint32_t* p = Qs + ks * 8 + qq;
            qf[ks][0] = p[0];
            qf[ks][1] = p[8 * AST];
            qf[ks][2] = p[4];
            qf[ks][3] = p[8 * AST + 4];
        }
    }

    float oacc[8][4];
    #pragma unroll
    for (int nt = 0; nt < 8; nt++)
        #pragma unroll
        for (int j = 0; j < 4; j++) oacc[nt][j] = 0.f;
    float den0 = 0.f, den1 = 0.f;

    uint32_t* Ps = sm + AOFF_P + wid * 16 * AST;  // per-warp 16-row slice

    for (int kt = 0; kt < SEQ; kt += 64) {
        __syncthreads();   // previous tile fully consumed (Ks/Vs); qf loaded
        // ---- cooperative K/V tile load (tf32): 64 rows x 16 float4
        #pragma unroll
        for (int i = 0; i < 4; i++) {
            int idx = tid + i * 256;          // 0..1023
            int rr = idx >> 4, cc = idx & 15;
            long base = ((long)(b * SEQ + kt + rr)) * EMB + h * HD + cc * 4;
            float4 kv = __ldg((const float4*)(K + base));
            float4 vv = __ldg((const float4*)(V + base));
            uint32_t* pk = sm + AOFF_K + rr * AST + cc * 4;
            uint32_t* pv = sm + AOFF_V + rr * AST + cc * 4;
            pk[0] = f2tf32(kv.x); pk[1] = f2tf32(kv.y); pk[2] = f2tf32(kv.z); pk[3] = f2tf32(kv.w);
            pv[0] = f2tf32(vv.x); pv[1] = f2tf32(vv.y); pv[2] = f2tf32(vv.z); pv[3] = f2tf32(vv.w);
        }
        __syncthreads();

        // ---- S = Q @ K^T  (warp: 16 rows x 64 keys)
        float sacc[8][4];
        #pragma unroll
        for (int nt = 0; nt < 8; nt++)
            #pragma unroll
            for (int j = 0; j < 4; j++) sacc[nt][j] = 0.f;

        #pragma unroll
        for (int ks = 0; ks < 8; ks++) {
            #pragma unroll
            for (int nt = 0; nt < 8; nt++) {
                const uint32_t* p = sm + AOFF_K + (nt * 8 + r) * AST + ks * 8 + qq;
                mma16n8k8(sacc[nt], qf[ks], p[0], p[4]);
            }
        }

        // ---- p = exp(sigmoid(s/8)); denom accumulate; stage tf32(P)
        #pragma unroll
        for (int nt = 0; nt < 8; nt++) {
            float p0, p1, p2, p3;
            // sigmoid(x) = 0.5 + 0.5*tanh(x/2); x = dot/8 -> tanh arg = dot/16
            p0 = fmaf(psign, tanh_fast(sacc[nt][0] * 0.0625f), 0.5f);
            p1 = fmaf(psign, tanh_fast(sacc[nt][1] * 0.0625f), 0.5f);
            p2 = fmaf(psign, tanh_fast(sacc[nt][2] * 0.0625f), 0.5f);
            p3 = fmaf(psign, tanh_fast(sacc[nt][3] * 0.0625f), 0.5f);
            p0 = __expf(p0); p1 = __expf(p1); p2 = __expf(p2); p3 = __expf(p3);
            den0 += p0 + p1;
            den1 += p2 + p3;
            uint32_t* ps = Ps + r * AST + nt * 8 + qq * 2;
            ps[0] = f2tf32(p0); ps[1] = f2tf32(p1);
            ps[8 * AST] = f2tf32(p2); ps[8 * AST + 1] = f2tf32(p3);
        }
        __syncwarp();

        // ---- O += P @ V   (contraction over 64 keys; V stored [key][dim])
        #pragma unroll
        for (int ks = 0; ks < 8; ks++) {
            uint32_t af[4];
            const uint32_t* pa = Ps + r * AST + ks * 8 + qq;
            af[0] = pa[0];
            af[1] = pa[8 * AST];
            af[2] = pa[4];
            af[3] = pa[8 * AST + 4];
            #pragma unroll
            for (int nt = 0; nt < 8; nt++) {
                const uint32_t* pb0 = sm + AOFF_V + (ks * 8 + qq) * AST + nt * 8 + r;
                mma16n8k8(oacc[nt], af, pb0[0], pb0[4 * AST]);
            }
        }
    }

    // ---- finalize: reduce denom across quad, scale, store
    den0 += __shfl_xor_sync(0xffffffffu, den0, 1);
    den0 += __shfl_xor_sync(0xffffffffu, den0, 2);
    den1 += __shfl_xor_sync(0xffffffffu, den1, 1);
    den1 += __shfl_xor_sync(0xffffffffu, den1, 2);
    float inv0 = 1.f / den0, inv1 = 1.f / den1;

    long row0 = (long)(b * SEQ + q0 + wid * 16 + r);
    #pragma unroll
    for (int nt = 0; nt < 8; nt++) {
        int col = h * HD + nt * 8 + qq * 2;
        float2 o0, o1;
        o0.x = oacc[nt][0] * inv0; o0.y = oacc[nt][1] * inv0;
        o1.x = oacc[nt][2] * inv1; o1.y = oacc[nt][3] * inv1;
        *(float2*)(O + row0 * EMB + col) = o0;
        *(float2*)(O + (row0 + 8) * EMB + col) = o1;
    }
}

// ----------------------------------------------------------------------------
extern "C" void kernel_launch(void* const* d_in, const int* in_sizes, int n_in,
                              void* d_out, int out_size)
{
    const float* queries = (const float*)d_in[0];
    const float* keys    = (const float*)d_in[1];
    const float* values  = (const float*)d_in[2];
    const float* Wq = (const float*)d_in[3];
    const float* bq = (const float*)d_in[4];
    const float* Wk = (const float*)d_in[5];
    const float* bk = (const float*)d_in[6];
    const float* Wv = (const float*)d_in[7];
    const float* bv = (const float*)d_in[8];
    const float* Wo = (const float*)d_in[9];
    const float* bo = (const float*)d_in[10];
    const int* indicator = (const int*)d_in[11];

    float *gq, *gk, *gv, *ga;
    cudaGetSymbolAddress((void**)&gq, g_q);
    cudaGetSymbolAddress((void**)&gk, g_k);
    cudaGetSymbolAddress((void**)&gv, g_v);
    cudaGetSymbolAddress((void**)&ga, g_attn);

    static int attr_set = 0;
    if (!attr_set) {
        cudaFuncSetAttribute(gemm_tf32_mma,
                             cudaFuncAttributeMaxDynamicSharedMemorySize, SM_WORDS * 4);
        cudaFuncSetAttribute(attn_mma,
                             cudaFuncAttributeMaxDynamicSharedMemorySize, A_SMEM_WORDS * 4);
        attr_set = 1;
    }

    dim3 qkv_grid(EMB / BN, MROWS / BM, 3);   // 384 CTAs
    gemm_tf32_mma<<<qkv_grid, 256, SM_WORDS * 4>>>(
        queries, Wq, bq, gq,
        keys,    Wk, bk, gk,
        values,  Wv, bv, gv);

    dim3 attn_grid(SEQ / 128, NH, BS_);       // 512 CTAs
    attn_mma<<<attn_grid, 256, A_SMEM_WORDS * 4>>>(gq, gk, gv, indicator, ga);

    dim3 o_grid(EMB / BN, MROWS / BM, 1);
    gemm_tf32_mma<<<o_grid, 256, SM_WORDS * 4>>>(
        ga, Wo, bo, (float*)d_out,
        ga, Wo, bo, (float*)d_out,
        ga, Wo, bo, (float*)d_out);
}

// round 7
// speedup vs baseline: 3.6506x; 1.0471x over previous
#include <cuda_runtime.h>
#include <cstdint>

#define BS_  2
#define SEQ  2048
#define EMB  1024
#define NH   16
#define HD   64
#define MROWS (BS_*SEQ)   // 4096

__device__ float g_q[BS_*SEQ*EMB];
__device__ float g_k[BS_*SEQ*EMB];
__device__ float g_v[BS_*SEQ*EMB];
__device__ float g_attn[BS_*SEQ*EMB];

__device__ __forceinline__ uint32_t f2tf32(float x) {
    uint32_t r; asm("cvt.rna.tf32.f32 %0, %1;" : "=r"(r) : "f"(x)); return r;
}
__device__ __forceinline__ float tanh_fast(float x) {
    float r; asm("tanh.approx.f32 %0, %1;" : "=f"(r) : "f"(x)); return r;
}
__device__ __forceinline__ void mma16n8k8(float c[4], const uint32_t a[4],
                                          const uint32_t b0, const uint32_t b1) {
    asm volatile(
        "mma.sync.aligned.m16n8k8.row.col.f32.tf32.tf32.f32 "
        "{%0,%1,%2,%3}, {%4,%5,%6,%7}, {%8,%9}, {%0,%1,%2,%3};"
        : "+f"(c[0]), "+f"(c[1]), "+f"(c[2]), "+f"(c[3])
        : "r"(a[0]), "r"(a[1]), "r"(a[2]), "r"(a[3]), "r"(b0), "r"(b1));
}

// exp(p) on [0,1]: degree-4 Chebyshev (max rel err ~1.8e-5), t = 2p-1
__device__ __forceinline__ float exp01(float p) {
    float t = fmaf(2.f, p, -1.f);
    float e = 0.00437510f;
    e = fmaf(e, t, 0.03501305f);
    e = fmaf(e, t, 0.20607264f);
    e = fmaf(e, t, 0.82412760f);
    e = fmaf(e, t, 1.64871112f);
    return e;
}

// ============================================================================
// Projection GEMM: C = tf32(A) @ tf32(W)^T + bias  (mma.sync HMMA tf32)
// CTA 256x128, warp 64x64, BK=32, double buffered, ONE sync per chunk.
// ============================================================================
#define BM 256
#define BN 128
#define BKC 32
#define PAD 36
#define OFF_A0 0
#define OFF_B0 (BM*PAD)
#define OFF_A1 (OFF_B0 + BN*PAD)
#define OFF_B1 (OFF_A1 + BM*PAD)
#define SM_WORDS (OFF_B1 + BN*PAD)
#define NCHUNK (EMB / BKC)

__global__ void __launch_bounds__(256, 1) gemm_tf32_mma(
    const float* __restrict__ A0, const float* __restrict__ W0, const float* __restrict__ b0_, float* __restrict__ C0,
    const float* __restrict__ A1, const float* __restrict__ W1, const float* __restrict__ b1_, float* __restrict__ C1,
    const float* __restrict__ A2, const float* __restrict__ W2, const float* __restrict__ b2_, float* __restrict__ C2)
{
    extern __shared__ uint32_t sm[];

    const float* A    = blockIdx.z == 0 ? A0 : (blockIdx.z == 1 ? A1 : A2);
    const float* W    = blockIdx.z == 0 ? W0 : (blockIdx.z == 1 ? W1 : W2);
    const float* bias = blockIdx.z == 0 ? b0_ : (blockIdx.z == 1 ? b1_ : b2_);
    float*       C    = blockIdx.z == 0 ? C0 : (blockIdx.z == 1 ? C1 : C2);

    const int tid  = threadIdx.x;
    const int lane = tid & 31;
    const int wid  = tid >> 5;
    const int wm   = wid >> 1;
    const int wn   = wid & 1;
    const int bm   = blockIdx.y * BM;
    const int bn   = blockIdx.x * BN;

    float4 ra[8], rb[4];
    const float* Ap = A + (long)bm * EMB;
    const float* Wp = W + (long)bn * EMB;

    auto ldgA = [&](int c) {
        int k0 = c * BKC;
        #pragma unroll
        for (int i = 0; i < 8; i++) {
            int id = tid + i * 256;
            ra[i] = __ldg((const float4*)(Ap + (long)(id >> 3) * EMB + k0 + (id & 7) * 4));
        }
        #pragma unroll
        for (int i = 0; i < 4; i++) {
            int id = tid + i * 256;
            rb[i] = __ldg((const float4*)(Wp + (long)(id >> 3) * EMB + k0 + (id & 7) * 4));
        }
    };
    auto stsAll = [&](int buf) {
        uint32_t* sA = sm + (buf ? OFF_A1 : OFF_A0);
        uint32_t* sB = sm + (buf ? OFF_B1 : OFF_B0);
        #pragma unroll
        for (int i = 0; i < 8; i++) {
            int id = tid + i * 256;
            uint32_t* p = sA + (id >> 3) * PAD + (id & 7) * 4;
            p[0] = f2tf32(ra[i].x); p[1] = f2tf32(ra[i].y);
            p[2] = f2tf32(ra[i].z); p[3] = f2tf32(ra[i].w);
        }
        #pragma unroll
        for (int i = 0; i < 4; i++) {
            int id = tid + i * 256;
            uint32_t* p = sB + (id >> 3) * PAD + (id & 7) * 4;
            p[0] = f2tf32(rb[i].x); p[1] = f2tf32(rb[i].y);
            p[2] = f2tf32(rb[i].z); p[3] = f2tf32(rb[i].w);
        }
    };

    float acc[4][8][4];
    #pragma unroll
    for (int mt = 0; mt < 4; mt++)
        #pragma unroll
        for (int nt = 0; nt < 8; nt++)
            #pragma unroll
            for (int j = 0; j < 4; j++) acc[mt][nt][j] = 0.f;

    ldgA(0);
    stsAll(0);
    ldgA(1);
    __syncthreads();

    const int arow = wm * 64 + (lane >> 2);
    const int brow = wn * 64 + (lane >> 2);
    const int kcol = lane & 3;

    for (int c = 0; c < NCHUNK; c++) {
        if (c + 1 < NCHUNK) stsAll((c + 1) & 1);   // hide STS under mma issue
        if (c + 2 < NCHUNK) ldgA(c + 2);

        const uint32_t* sA = sm + ((c & 1) ? OFF_A1 : OFF_A0);
        const uint32_t* sB = sm + ((c & 1) ? OFF_B1 : OFF_B0);

        #pragma unroll
        for (int ks = 0; ks < 4; ks++) {
            int kb = ks * 8 + kcol;
            uint32_t af[4][4], bf[8][2];
            #pragma unroll
            for (int mt = 0; mt < 4; mt++) {
                const uint32_t* p = sA + (arow + mt * 16) * PAD + kb;
                af[mt][0] = p[0];
                af[mt][1] = p[8 * PAD];
                af[mt][2] = p[4];
                af[mt][3] = p[8 * PAD + 4];
            }
            #pragma unroll
            for (int nt = 0; nt < 8; nt++) {
                const uint32_t* p = sB + (brow + nt * 8) * PAD + kb;
                bf[nt][0] = p[0];
                bf[nt][1] = p[4];
            }
            #pragma unroll
            for (int mt = 0; mt < 4; mt++)
                #pragma unroll
                for (int nt = 0; nt < 8; nt++)
                    mma16n8k8(acc[mt][nt], af[mt], bf[nt][0], bf[nt][1]);
        }
        __syncthreads();
    }

    #pragma unroll
    for (int mt = 0; mt < 4; mt++) {
        int r0 = bm + wm * 64 + mt * 16 + (lane >> 2);
        #pragma unroll
        for (int nt = 0; nt < 8; nt++) {
            int col = bn + wn * 64 + nt * 8 + (lane & 3) * 2;
            float2 bb = *(const float2*)(bias + col);
            float2 o0, o1;
            o0.x = acc[mt][nt][0] + bb.x; o0.y = acc[mt][nt][1] + bb.y;
            o1.x = acc[mt][nt][2] + bb.x; o1.y = acc[mt][nt][3] + bb.y;
            *(float2*)(C + (long)r0 * EMB + col) = o0;
            *(float2*)(C + (long)(r0 + 8) * EMB + col) = o1;
        }
    }
}

// ============================================================================
// Attention via mma.sync tf32 (R5-proven fragment math) with:
//   - double-buffered K/V smem + register prefetch (1 sync/tile)
//   - poly exp01 (1 MUFU/element instead of 2)
// CTA: 128 queries x one (b,h); 8 warps x 16 rows; 64-key tiles.
// smem words (stride 68): K0@0 K1@4352 V0@8704 V1@13056 P@17408 (128x68)
// ============================================================================
#define AST 68
#define AOFF_K0 0
#define AOFF_K1 (64*AST)
#define AOFF_V0 (2*64*AST)
#define AOFF_V1 (3*64*AST)
#define AOFF_P  (4*64*AST)
#define A_WORDS (AOFF_P + 128*AST)   // 26112 words = 104448 B

__global__ void __launch_bounds__(256, 1) attn_mma(
    const float* __restrict__ Q, const float* __restrict__ K,
    const float* __restrict__ V, const int* __restrict__ indicator,
    float* __restrict__ O)
{
    extern __shared__ uint32_t sm[];
    const int tid  = threadIdx.x;
    const int lane = tid & 31;
    const int wid  = tid >> 5;             // 0..7
    const int b    = blockIdx.z;
    const int h    = blockIdx.y;
    const int q0   = blockIdx.x * 128;
    const int r    = lane >> 2;            // 0..7
    const int qq   = lane & 3;             // 0..3

    const float psign = __ldg(indicator) ? -0.5f : 0.5f;

    // ---- stage FULL Q tile [128 rows][64 dims] into P region temporarily
    {
        uint32_t* Qs = sm + AOFF_P;
        #pragma unroll
        for (int i = 0; i < 8; i++) {
            int idx = tid + i * 256;          // 0..2047
            int rr = idx >> 4, cc = idx & 15; // 128 rows x 16 float4
            float4 v = __ldg((const float4*)(Q + ((long)(b * SEQ + q0 + rr)) * EMB + h * HD + cc * 4));
            uint32_t* p = Qs + rr * AST + cc * 4;
            p[0] = f2tf32(v.x); p[1] = f2tf32(v.y); p[2] = f2tf32(v.z); p[3] = f2tf32(v.w);
        }
    }
    __syncthreads();

    uint32_t qf[8][4];
    {
        const uint32_t* Qs = sm + AOFF_P + (wid * 16 + r) * AST;
        #pragma unroll
        for (int ks = 0; ks < 8; ks++) {
            const uint32_t* p = Qs + ks * 8 + qq;
            qf[ks][0] = p[0];
            qf[ks][1] = p[8 * AST];
            qf[ks][2] = p[4];
            qf[ks][3] = p[8 * AST + 4];
        }
    }
    __syncthreads();   // Q frags in regs; P region free for reuse

    // K/V register prefetch state (4 float4 each)
    float4 rk[4], rv[4];
    const int ld_rr = tid >> 4;        // 0..15 (row group base; 4 rows apart)
    const int ld_cc = tid & 15;        // float4 column

    auto ldgKV = [&](int kt) {
        #pragma unroll
        for (int i = 0; i < 4; i++) {
            int rr = ld_rr + i * 16;
            long base = ((long)(b * SEQ + kt + rr)) * EMB + h * HD + ld_cc * 4;
            rk[i] = __ldg((const float4*)(K + base));
            rv[i] = __ldg((const float4*)(V + base));
        }
    };
    auto stsKV = [&](int buf) {
        uint32_t* pk0 = sm + (buf ? AOFF_K1 : AOFF_K0);
        uint32_t* pv0 = sm + (buf ? AOFF_V1 : AOFF_V0);
        #pragma unroll
        for (int i = 0; i < 4; i++) {
            int rr = ld_rr + i * 16;
            uint32_t* pk = pk0 + rr * AST + ld_cc * 4;
            uint32_t* pv = pv0 + rr * AST + ld_cc * 4;
            pk[0] = f2tf32(rk[i].x); pk[1] = f2tf32(rk[i].y);
            pk[2] = f2tf32(rk[i].z); pk[3] = f2tf32(rk[i].w);
            pv[0] = f2tf32(rv[i].x); pv[1] = f2tf32(rv[i].y);
            pv[2] = f2tf32(rv[i].z); pv[3] = f2tf32(rv[i].w);
        }
    };

    float oacc[8][4];
    #pragma unroll
    for (int nt = 0; nt < 8; nt++)
        #pragma unroll
        for (int j = 0; j < 4; j++) oacc[nt][j] = 0.f;
    float den0 = 0.f, den1 = 0.f;

    uint32_t* Ps = sm + AOFF_P + wid * 16 * AST;  // per-warp 16-row slice

    ldgKV(0);
    stsKV(0);
    ldgKV(64);
    __syncthreads();

    const int NT = SEQ / 64;   // 32 tiles
    for (int t = 0; t < NT; t++) {
        if (t + 1 < NT) stsKV((t + 1) & 1);       // from regs (tile t+1)
        if (t + 2 < NT) ldgKV((t + 2) * 64);      // prefetch tile t+2

        const uint32_t* Kb = sm + ((t & 1) ? AOFF_K1 : AOFF_K0);
        const uint32_t* Vb = sm + ((t & 1) ? AOFF_V1 : AOFF_V0);

        // ---- S = Q @ K^T  (warp: 16 rows x 64 keys)
        float sacc[8][4];
        #pragma unroll
        for (int nt = 0; nt < 8; nt++)
            #pragma unroll
            for (int j = 0; j < 4; j++) sacc[nt][j] = 0.f;

        #pragma unroll
        for (int ks = 0; ks < 8; ks++) {
            #pragma unroll
            for (int nt = 0; nt < 8; nt++) {
                const uint32_t* p = Kb + (nt * 8 + r) * AST + ks * 8 + qq;
                mma16n8k8(sacc[nt], qf[ks], p[0], p[4]);
            }
        }

        // ---- p = exp01(sigmoid(s/8)); denom accumulate; stage tf32(P)
        #pragma unroll
        for (int nt = 0; nt < 8; nt++) {
            float p0 = fmaf(psign, tanh_fast(sacc[nt][0] * 0.0625f), 0.5f);
            float p1 = fmaf(psign, tanh_fast(sacc[nt][1] * 0.0625f), 0.5f);
            float p2 = fmaf(psign, tanh_fast(sacc[nt][2] * 0.0625f), 0.5f);
            float p3 = fmaf(psign, tanh_fast(sacc[nt][3] * 0.0625f), 0.5f);
            p0 = exp01(p0); p1 = exp01(p1); p2 = exp01(p2); p3 = exp01(p3);
            den0 += p0 + p1;
            den1 += p2 + p3;
            uint32_t* ps = Ps + r * AST + nt * 8 + qq * 2;
            ps[0] = f2tf32(p0); ps[1] = f2tf32(p1);
            ps[8 * AST] = f2tf32(p2); ps[8 * AST + 1] = f2tf32(p3);
        }
        __syncwarp();

        // ---- O += P @ V   (contraction over 64 keys; V stored [key][dim])
        #pragma unroll
        for (int ks = 0; ks < 8; ks++) {
            uint32_t af[4];
            const uint32_t* pa = Ps + r * AST + ks * 8 + qq;
            af[0] = pa[0];
            af[1] = pa[8 * AST];
            af[2] = pa[4];
            af[3] = pa[8 * AST + 4];
            #pragma unroll
            for (int nt = 0; nt < 8; nt++) {
                const uint32_t* pb0 = Vb + (ks * 8 + qq) * AST + nt * 8 + r;
                mma16n8k8(oacc[nt], af, pb0[0], pb0[4 * AST]);
            }
        }
        __syncthreads();
    }

    // ---- finalize: reduce denom across quad, scale, store
    den0 += __shfl_xor_sync(0xffffffffu, den0, 1);
    den0 += __shfl_xor_sync(0xffffffffu, den0, 2);
    den1 += __shfl_xor_sync(0xffffffffu, den1, 1);
    den1 += __shfl_xor_sync(0xffffffffu, den1, 2);
    float inv0 = 1.f / den0, inv1 = 1.f / den1;

    long row0 = (long)(b * SEQ + q0 + wid * 16 + r);
    #pragma unroll
    for (int nt = 0; nt < 8; nt++) {
        int col = h * HD + nt * 8 + qq * 2;
        float2 o0, o1;
        o0.x = oacc[nt][0] * inv0; o0.y = oacc[nt][1] * inv0;
        o1.x = oacc[nt][2] * inv1; o1.y = oacc[nt][3] * inv1;
        *(float2*)(O + row0 * EMB + col) = o0;
        *(float2*)(O + (row0 + 8) * EMB + col) = o1;
    }
}

// ----------------------------------------------------------------------------
extern "C" void kernel_launch(void* const* d_in, const int* in_sizes, int n_in,
                              void* d_out, int out_size)
{
    const float* queries = (const float*)d_in[0];
    const float* keys    = (const float*)d_in[1];
    const float* values  = (const float*)d_in[2];
    const float* Wq = (const float*)d_in[3];
    const float* bq = (const float*)d_in[4];
    const float* Wk = (const float*)d_in[5];
    const float* bk = (const float*)d_in[6];
    const float* Wv = (const float*)d_in[7];
    const float* bv = (const float*)d_in[8];
    const float* Wo = (const float*)d_in[9];
    const float* bo = (const float*)d_in[10];
    const int* indicator = (const int*)d_in[11];

    float *gq, *gk, *gv, *ga;
    cudaGetSymbolAddress((void**)&gq, g_q);
    cudaGetSymbolAddress((void**)&gk, g_k);
    cudaGetSymbolAddress((void**)&gv, g_v);
    cudaGetSymbolAddress((void**)&ga, g_attn);

    static int attr_set = 0;
    if (!attr_set) {
        cudaFuncSetAttribute(gemm_tf32_mma,
                             cudaFuncAttributeMaxDynamicSharedMemorySize, SM_WORDS * 4);
        cudaFuncSetAttribute(attn_mma,
                             cudaFuncAttributeMaxDynamicSharedMemorySize, A_WORDS * 4);
        attr_set = 1;
    }

    dim3 qkv_grid(EMB / BN, MROWS / BM, 3);   // 384 CTAs
    gemm_tf32_mma<<<qkv_grid, 256, SM_WORDS * 4>>>(
        queries, Wq, bq, gq,
        keys,    Wk, bk, gk,
        values,  Wv, bv, gv);

    dim3 attn_grid(SEQ / 128, NH, BS_);       // 512 CTAs
    attn_mma<<<attn_grid, 256, A_WORDS * 4>>>(gq, gk, gv, indicator, ga);

    dim3 o_grid(EMB / BN, MROWS / BM, 1);
    gemm_tf32_mma<<<o_grid, 256, SM_WORDS * 4>>>(
        ga, Wo, bo, (float*)d_out,
        ga, Wo, bo, (float*)d_out,
        ga, Wo, bo, (float*)d_out);
}

// round 8
// speedup vs baseline: 4.2257x; 1.1575x over previous
#include <cuda_runtime.h>
#include <cstdint>

#define BS_  2
#define SEQ  2048
#define EMB  1024
#define NH   16
#define HD   64
#define MROWS (BS_*SEQ)   // 4096

__device__ float g_q[BS_*SEQ*EMB];
__device__ float g_k[BS_*SEQ*EMB];
__device__ float g_vt[BS_*NH*HD*SEQ];   // V transposed: [b][h][d][s]
__device__ float g_attn[BS_*SEQ*EMB];

__device__ __forceinline__ uint32_t f2tf32(float x) {
    uint32_t r; asm("cvt.rna.tf32.f32 %0, %1;" : "=r"(r) : "f"(x)); return r;
}
__device__ __forceinline__ float tanh_fast(float x) {
    float r; asm("tanh.approx.f32 %0, %1;" : "=f"(r) : "f"(x)); return r;
}
__device__ __forceinline__ uint32_t smem_u32(const void* p) {
    uint32_t a;
    asm("{ .reg .u64 t; cvta.to.shared.u64 t, %1; cvt.u32.u64 %0, t; }"
        : "=r"(a) : "l"(p));
    return a;
}
__device__ __forceinline__ void ldsm4(uint32_t r[4], uint32_t a) {
    asm volatile("ldmatrix.sync.aligned.m8n8.x4.shared.b16 {%0,%1,%2,%3}, [%4];"
        : "=r"(r[0]), "=r"(r[1]), "=r"(r[2]), "=r"(r[3]) : "r"(a));
}
__device__ __forceinline__ void mma16n8k8(float c[4], const uint32_t a[4],
                                          const uint32_t b0, const uint32_t b1) {
    asm volatile(
        "mma.sync.aligned.m16n8k8.row.col.f32.tf32.tf32.f32 "
        "{%0,%1,%2,%3}, {%4,%5,%6,%7}, {%8,%9}, {%0,%1,%2,%3};"
        : "+f"(c[0]), "+f"(c[1]), "+f"(c[2]), "+f"(c[3])
        : "r"(a[0]), "r"(a[1]), "r"(a[2]), "r"(a[3]), "r"(b0), "r"(b1));
}
// exp(p) on [0,1]: degree-4 Chebyshev (max rel err ~1.8e-5), t = 2p-1
__device__ __forceinline__ float exp01(float p) {
    float t = fmaf(2.f, p, -1.f);
    float e = 0.00437510f;
    e = fmaf(e, t, 0.03501305f);
    e = fmaf(e, t, 0.20607264f);
    e = fmaf(e, t, 0.82412760f);
    e = fmaf(e, t, 1.64871112f);
    return e;
}

// ============================================================================
// Projection GEMM: C = tf32(A) @ tf32(W)^T + bias.  CTA 128x128, warp 32x64,
// BK=32, double buffered, 1 sync/chunk, ldmatrix frags, 2 CTAs/SM.
// vt_z: problem index whose C is written transposed as Vt[b][h][d][s] (-1 off)
// ============================================================================
#define BM 128
#define BN 128
#define BKC 32
#define PAD 36
#define OFF_A0 0
#define OFF_B0 (BM*PAD)
#define OFF_A1 (OFF_B0 + BN*PAD)
#define OFF_B1 (OFF_A1 + BM*PAD)
#define SM_WORDS (OFF_B1 + BN*PAD)   // 18432 words = 73728 B
#define NCHUNK (EMB / BKC)

__global__ void __launch_bounds__(256, 2) gemm_tf32_mma(
    const float* __restrict__ A0, const float* __restrict__ W0, const float* __restrict__ b0_, float* __restrict__ C0,
    const float* __restrict__ A1, const float* __restrict__ W1, const float* __restrict__ b1_, float* __restrict__ C1,
    const float* __restrict__ A2, const float* __restrict__ W2, const float* __restrict__ b2_, float* __restrict__ C2,
    int vt_z)
{
    extern __shared__ uint32_t sm[];
    const uint32_t sb = smem_u32(sm);

    const float* A    = blockIdx.z == 0 ? A0 : (blockIdx.z == 1 ? A1 : A2);
    const float* W    = blockIdx.z == 0 ? W0 : (blockIdx.z == 1 ? W1 : W2);
    const float* bias = blockIdx.z == 0 ? b0_ : (blockIdx.z == 1 ? b1_ : b2_);
    float*       C    = blockIdx.z == 0 ? C0 : (blockIdx.z == 1 ? C1 : C2);
    const bool tpose  = ((int)blockIdx.z == vt_z);

    const int tid  = threadIdx.x;
    const int lane = tid & 31;
    const int wid  = tid >> 5;
    const int wm   = wid >> 1;     // 0..3
    const int wn   = wid & 1;      // 0..1
    const int bm   = blockIdx.y * BM;
    const int bn   = blockIdx.x * BN;

    float4 ra[4], rb[4];
    const float* Ap = A + (long)bm * EMB;
    const float* Wp = W + (long)bn * EMB;

    auto ldgA = [&](int c) {
        int k0 = c * BKC;
        #pragma unroll
        for (int i = 0; i < 4; i++) {
            int id = tid + i * 256;   // 0..1023: 128 rows x 8 f4
            ra[i] = __ldg((const float4*)(Ap + (long)(id >> 3) * EMB + k0 + (id & 7) * 4));
            rb[i] = __ldg((const float4*)(Wp + (long)(id >> 3) * EMB + k0 + (id & 7) * 4));
        }
    };
    auto stsAll = [&](int buf) {
        uint32_t* sA = sm + (buf ? OFF_A1 : OFF_A0);
        uint32_t* sB = sm + (buf ? OFF_B1 : OFF_B0);
        #pragma unroll
        for (int i = 0; i < 4; i++) {
            int id = tid + i * 256;
            uint32_t* p = sA + (id >> 3) * PAD + (id & 7) * 4;
            p[0] = f2tf32(ra[i].x); p[1] = f2tf32(ra[i].y);
            p[2] = f2tf32(ra[i].z); p[3] = f2tf32(ra[i].w);
            uint32_t* q = sB + (id >> 3) * PAD + (id & 7) * 4;
            q[0] = f2tf32(rb[i].x); q[1] = f2tf32(rb[i].y);
            q[2] = f2tf32(rb[i].z); q[3] = f2tf32(rb[i].w);
        }
    };

    float acc[2][8][4];
    #pragma unroll
    for (int mt = 0; mt < 2; mt++)
        #pragma unroll
        for (int nt = 0; nt < 8; nt++)
            #pragma unroll
            for (int j = 0; j < 4; j++) acc[mt][nt][j] = 0.f;

    ldgA(0);
    stsAll(0);
    ldgA(1);
    __syncthreads();

    // ldmatrix lane-address components (word offsets within tile)
    const int a_row = (lane & 7) + 8 * ((lane >> 3) & 1);   // + mt*16 + wm*32
    const int a_kw  = 4 * (lane >> 4);                      // + ks*8
    const int b_row = (lane & 7) + 8 * (lane >> 4);         // + g*16 + wn*64
    const int b_kw  = 4 * ((lane >> 3) & 1);                // + ks*8

    for (int c = 0; c < NCHUNK; c++) {
        if (c + 1 < NCHUNK) stsAll((c + 1) & 1);
        if (c + 2 < NCHUNK) ldgA(c + 2);

        const uint32_t offA = (c & 1) ? OFF_A1 : OFF_A0;
        const uint32_t offB = (c & 1) ? OFF_B1 : OFF_B0;

        #pragma unroll
        for (int ks = 0; ks < 4; ks++) {
            uint32_t af[2][4], bf[8][2];
            #pragma unroll
            for (int mt = 0; mt < 2; mt++) {
                uint32_t addr = sb + 4u * (offA + (uint32_t)((wm * 32 + mt * 16 + a_row) * PAD + ks * 8 + a_kw));
                ldsm4(af[mt], addr);
            }
            #pragma unroll
            for (int g = 0; g < 4; g++) {
                uint32_t tmp[4];
                uint32_t addr = sb + 4u * (offB + (uint32_t)((wn * 64 + g * 16 + b_row) * PAD + ks * 8 + b_kw));
                ldsm4(tmp, addr);
                bf[2 * g][0] = tmp[0]; bf[2 * g][1] = tmp[1];
                bf[2 * g + 1][0] = tmp[2]; bf[2 * g + 1][1] = tmp[3];
            }
            #pragma unroll
            for (int mt = 0; mt < 2; mt++)
                #pragma unroll
                for (int nt = 0; nt < 8; nt++)
                    mma16n8k8(acc[mt][nt], af[mt], bf[nt][0], bf[nt][1]);
        }
        __syncthreads();
    }

    if (!tpose) {
        #pragma unroll
        for (int mt = 0; mt < 2; mt++) {
            int r0 = bm + wm * 32 + mt * 16 + (lane >> 2);
            #pragma unroll
            for (int nt = 0; nt < 8; nt++) {
                int col = bn + wn * 64 + nt * 8 + (lane & 3) * 2;
                float2 bb = *(const float2*)(bias + col);
                float2 o0, o1;
                o0.x = acc[mt][nt][0] + bb.x; o0.y = acc[mt][nt][1] + bb.y;
                o1.x = acc[mt][nt][2] + bb.x; o1.y = acc[mt][nt][3] + bb.y;
                *(float2*)(C + (long)r0 * EMB + col) = o0;
                *(float2*)(C + (long)(r0 + 8) * EMB + col) = o1;
            }
        }
    } else {
        // write C transposed per (b,h): Vt[((b*NH+h)*HD + d)*SEQ + s]
        #pragma unroll
        for (int mt = 0; mt < 2; mt++) {
            int r0 = bm + wm * 32 + mt * 16 + (lane >> 2);
            int b_ = r0 >> 11, s = r0 & (SEQ - 1);
            #pragma unroll
            for (int nt = 0; nt < 8; nt++) {
                int col = bn + wn * 64 + nt * 8 + (lane & 3) * 2;
                int h = col >> 6, d = col & 63;
                float2 bb = *(const float2*)(bias + col);
                float* base = C + ((long)((b_ * NH + h) * HD + d)) * SEQ + s;
                base[0]       = acc[mt][nt][0] + bb.x;
                base[SEQ]     = acc[mt][nt][1] + bb.y;
                base[8]       = acc[mt][nt][2] + bb.x;
                base[SEQ + 8] = acc[mt][nt][3] + bb.y;
            }
        }
    }
}

// ============================================================================
// Attention via mma.sync tf32 + ldmatrix fragments.
// w = sigmoid(qk/8) in [0,1] -> exp(w) in [1,e]: single pass, no running max.
// CTA: 64 queries x one (b,h); 4 warps x 16 rows; 64-key tiles; 2 CTAs/SM.
// K tiles [key][dim], V tiles from g_vt as [dim][key], P [qrow][key].
// ============================================================================
#define AST 68
#define AOFF_K0 0
#define AOFF_K1 (64*AST)
#define AOFF_V0 (2*64*AST)
#define AOFF_V1 (3*64*AST)
#define AOFF_P  (4*64*AST)
#define A_WORDS (AOFF_P + 64*AST)   // 21760 words = 87040 B

__global__ void __launch_bounds__(128, 2) attn_mma(
    const float* __restrict__ Q, const float* __restrict__ K,
    const float* __restrict__ Vt, const int* __restrict__ indicator,
    float* __restrict__ O)
{
    extern __shared__ uint32_t sm[];
    const uint32_t sb = smem_u32(sm);
    const int tid  = threadIdx.x;
    const int lane = tid & 31;
    const int wid  = tid >> 5;             // 0..3
    const int b    = blockIdx.z;
    const int h    = blockIdx.y;
    const int q0   = blockIdx.x * 64;
    const int r    = lane >> 2;            // 0..7
    const int qq   = lane & 3;             // 0..3

    const float psign = __ldg(indicator) ? -0.5f : 0.5f;

    // ldmatrix lane-address components
    const int a_row = (lane & 7) + 8 * ((lane >> 3) & 1);   // A-pattern (Q, P)
    const int a_kw  = 4 * (lane >> 4);
    const int b_row = (lane & 7) + 8 * (lane >> 4);         // B-pattern (K, Vt)
    const int b_kw  = 4 * ((lane >> 3) & 1);

    // ---- stage Q tile [64 rows][64 dims] into P region temporarily
    #pragma unroll
    for (int i = 0; i < 8; i++) {
        int idx = tid + i * 128;          // 0..1023
        int rr = idx >> 4, cc = idx & 15; // 64 rows x 16 f4
        float4 v = __ldg((const float4*)(Q + ((long)(b * SEQ + q0 + rr)) * EMB + h * HD + cc * 4));
        uint32_t* p = sm + AOFF_P + rr * AST + cc * 4;
        p[0] = f2tf32(v.x); p[1] = f2tf32(v.y); p[2] = f2tf32(v.z); p[3] = f2tf32(v.w);
    }
    __syncthreads();

    uint32_t qf[8][4];
    #pragma unroll
    for (int ks = 0; ks < 8; ks++) {
        uint32_t addr = sb + 4u * (uint32_t)(AOFF_P + (wid * 16 + a_row) * AST + ks * 8 + a_kw);
        ldsm4(qf[ks], addr);
    }
    __syncthreads();   // Q frags in regs; P region free

    // K/V prefetch registers
    float4 rk[8], rv[8];
    auto ldgKV = [&](int kt) {
        #pragma unroll
        for (int i = 0; i < 8; i++) {
            int idx = tid + i * 128;
            int rr = idx >> 4, cc = idx & 15;
            rk[i] = __ldg((const float4*)(K + ((long)(b * SEQ + kt + rr)) * EMB + h * HD + cc * 4));
            rv[i] = __ldg((const float4*)(Vt + ((long)((b * NH + h) * HD + rr)) * SEQ + kt + cc * 4));
        }
    };
    auto stsKV = [&](int buf) {
        uint32_t* pk0 = sm + (buf ? AOFF_K1 : AOFF_K0);
        uint32_t* pv0 = sm + (buf ? AOFF_V1 : AOFF_V0);
        #pragma unroll
        for (int i = 0; i < 8; i++) {
            int idx = tid + i * 128;
            int rr = idx >> 4, cc = idx & 15;
            uint32_t* pk = pk0 + rr * AST + cc * 4;
            pk[0] = f2tf32(rk[i].x); pk[1] = f2tf32(rk[i].y);
            pk[2] = f2tf32(rk[i].z); pk[3] = f2tf32(rk[i].w);
            uint32_t* pv = pv0 + rr * AST + cc * 4;
            pv[0] = f2tf32(rv[i].x); pv[1] = f2tf32(rv[i].y);
            pv[2] = f2tf32(rv[i].z); pv[3] = f2tf32(rv[i].w);
        }
    };

    float oacc[8][4];
    #pragma unroll
    for (int nt = 0; nt < 8; nt++)
        #pragma unroll
        for (int j = 0; j < 4; j++) oacc[nt][j] = 0.f;
    float den0 = 0.f, den1 = 0.f;

    ldgKV(0);
    stsKV(0);
    ldgKV(64);
    __syncthreads();

    const int NT = SEQ / 64;
    for (int t = 0; t < NT; t++) {
        if (t + 1 < NT) stsKV((t + 1) & 1);
        if (t + 2 < NT) ldgKV((t + 2) * 64);

        const uint32_t offK = (t & 1) ? AOFF_K1 : AOFF_K0;
        const uint32_t offV = (t & 1) ? AOFF_V1 : AOFF_V0;

        // ---- S = Q @ K^T
        float sacc[8][4];
        #pragma unroll
        for (int nt = 0; nt < 8; nt++)
            #pragma unroll
            for (int j = 0; j < 4; j++) sacc[nt][j] = 0.f;

        #pragma unroll
        for (int ks = 0; ks < 8; ks++) {
            #pragma unroll
            for (int g = 0; g < 4; g++) {
                uint32_t bfr[4];
                uint32_t addr = sb + 4u * (offK + (uint32_t)((g * 16 + b_row) * AST + ks * 8 + b_kw));
                ldsm4(bfr, addr);
                mma16n8k8(sacc[2 * g],     qf[ks], bfr[0], bfr[1]);
                mma16n8k8(sacc[2 * g + 1], qf[ks], bfr[2], bfr[3]);
            }
        }

        // ---- p = exp01(sigmoid(s/8)); stage tf32(P) as float2 STS
        uint32_t* Ps = sm + AOFF_P + wid * 16 * AST;
        #pragma unroll
        for (int nt = 0; nt < 8; nt++) {
            float p0 = fmaf(psign, tanh_fast(sacc[nt][0] * 0.0625f), 0.5f);
            float p1 = fmaf(psign, tanh_fast(sacc[nt][1] * 0.0625f), 0.5f);
            float p2 = fmaf(psign, tanh_fast(sacc[nt][2] * 0.0625f), 0.5f);
            float p3 = fmaf(psign, tanh_fast(sacc[nt][3] * 0.0625f), 0.5f);
            p0 = exp01(p0); p1 = exp01(p1); p2 = exp01(p2); p3 = exp01(p3);
            den0 += p0 + p1;
            den1 += p2 + p3;
            uint32_t* ps = Ps + r * AST + nt * 8 + qq * 2;
            uint2 w0 = make_uint2(f2tf32(p0), f2tf32(p1));
            uint2 w1 = make_uint2(f2tf32(p2), f2tf32(p3));
            *(uint2*)ps = w0;
            *(uint2*)(ps + 8 * AST) = w1;
        }
        __syncwarp();

        // ---- O += P @ V  (P A-frags and Vt B-frags via ldmatrix)
        #pragma unroll
        for (int ks = 0; ks < 8; ks++) {
            uint32_t af[4];
            uint32_t paddr = sb + 4u * (uint32_t)(AOFF_P + (wid * 16 + a_row) * AST + ks * 8 + a_kw);
            ldsm4(af, paddr);
            #pragma unroll
            for (int g = 0; g < 4; g++) {
                uint32_t bfr[4];
                uint32_t addr = sb + 4u * (offV + (uint32_t)((g * 16 + b_row) * AST + ks * 8 + b_kw));
                ldsm4(bfr, addr);
                mma16n8k8(oacc[2 * g],     af, bfr[0], bfr[1]);
                mma16n8k8(oacc[2 * g + 1], af, bfr[2], bfr[3]);
            }
        }
        __syncthreads();
    }

    den0 += __shfl_xor_sync(0xffffffffu, den0, 1);
    den0 += __shfl_xor_sync(0xffffffffu, den0, 2);
    den1 += __shfl_xor_sync(0xffffffffu, den1, 1);
    den1 += __shfl_xor_sync(0xffffffffu, den1, 2);
    float inv0 = 1.f / den0, inv1 = 1.f / den1;

    long row0 = (long)(b * SEQ + q0 + wid * 16 + r);
    #pragma unroll
    for (int nt = 0; nt < 8; nt++) {
        int col = h * HD + nt * 8 + qq * 2;
        float2 o0, o1;
        o0.x = oacc[nt][0] * inv0; o0.y = oacc[nt][1] * inv0;
        o1.x = oacc[nt][2] * inv1; o1.y = oacc[nt][3] * inv1;
        *(float2*)(O + row0 * EMB + col) = o0;
        *(float2*)(O + (row0 + 8) * EMB + col) = o1;
    }
}

// ----------------------------------------------------------------------------
extern "C" void kernel_launch(void* const* d_in, const int* in_sizes, int n_in,
                              void* d_out, int out_size)
{
    const float* queries = (const float*)d_in[0];
    const float* keys    = (const float*)d_in[1];
    const float* values  = (const float*)d_in[2];
    const float* Wq = (const float*)d_in[3];
    const float* bq = (const float*)d_in[4];
    const float* Wk = (const float*)d_in[5];
    const float* bk = (const float*)d_in[6];
    const float* Wv = (const float*)d_in[7];
    const float* bv = (const float*)d_in[8];
    const float* Wo = (const float*)d_in[9];
    const float* bo = (const float*)d_in[10];
    const int* indicator = (const int*)d_in[11];

    float *gq, *gk, *gvt, *ga;
    cudaGetSymbolAddress((void**)&gq, g_q);
    cudaGetSymbolAddress((void**)&gk, g_k);
    cudaGetSymbolAddress((void**)&gvt, g_vt);
    cudaGetSymbolAddress((void**)&ga, g_attn);

    static int attr_set = 0;
    if (!attr_set) {
        cudaFuncSetAttribute(gemm_tf32_mma,
                             cudaFuncAttributeMaxDynamicSharedMemorySize, SM_WORDS * 4);
        cudaFuncSetAttribute(attn_mma,
                             cudaFuncAttributeMaxDynamicSharedMemorySize, A_WORDS * 4);
        attr_set = 1;
    }

    dim3 qkv_grid(EMB / BN, MROWS / BM, 3);   // (8, 32, 3) = 768 CTAs
    gemm_tf32_mma<<<qkv_grid, 256, SM_WORDS * 4>>>(
        queries, Wq, bq, gq,
        keys,    Wk, bk, gk,
        values,  Wv, bv, gvt,
        2 /* transpose problem z==2 (V) */);

    dim3 attn_grid(SEQ / 64, NH, BS_);        // (32, 16, 2) = 1024 CTAs
    attn_mma<<<attn_grid, 128, A_WORDS * 4>>>(gq, gk, gvt, indicator, ga);

    dim3 o_grid(EMB / BN, MROWS / BM, 1);     // (8, 32)
    gemm_tf32_mma<<<o_grid, 256, SM_WORDS * 4>>>(
        ga, Wo, bo, (float*)d_out,
        ga, Wo, bo, (float*)d_out,
        ga, Wo, bo, (float*)d_out,
        -1);
}

// round 9
// speedup vs baseline: 4.4454x; 1.0520x over previous
#include <cuda_runtime.h>
#include <cstdint>

#define BS_  2
#define SEQ  2048
#define EMB  1024
#define NH   16
#define HD   64
#define MROWS (BS_*SEQ)   // 4096

// scratch (device globals)
__device__ float g_q[BS_*SEQ*EMB];
__device__ float g_k[BS_*SEQ*EMB];
__device__ float g_vt[BS_*NH*HD*SEQ];   // V transposed: [b][h][d][s]
__device__ float g_attn[BS_*SEQ*EMB];
// tf32-pre-rounded copies of inputs
__device__ float g_aq[BS_*SEQ*EMB];
__device__ float g_ak[BS_*SEQ*EMB];
__device__ float g_av[BS_*SEQ*EMB];
__device__ float g_wq[EMB*EMB];
__device__ float g_wk[EMB*EMB];
__device__ float g_wv[EMB*EMB];
__device__ float g_wo[EMB*EMB];

__device__ __forceinline__ uint32_t f2tf32(float x) {
    uint32_t r; asm("cvt.rna.tf32.f32 %0, %1;" : "=r"(r) : "f"(x)); return r;
}
__device__ __forceinline__ float rnd_tf32(float x) {
    return __uint_as_float(f2tf32(x));
}
__device__ __forceinline__ float tanh_fast(float x) {
    float r; asm("tanh.approx.f32 %0, %1;" : "=f"(r) : "f"(x)); return r;
}
__device__ __forceinline__ uint32_t smem_u32(const void* p) {
    uint32_t a;
    asm("{ .reg .u64 t; cvta.to.shared.u64 t, %1; cvt.u32.u64 %0, t; }"
        : "=r"(a) : "l"(p));
    return a;
}
__device__ __forceinline__ void ldsm4(uint32_t r[4], uint32_t a) {
    asm volatile("ldmatrix.sync.aligned.m8n8.x4.shared.b16 {%0,%1,%2,%3}, [%4];"
        : "=r"(r[0]), "=r"(r[1]), "=r"(r[2]), "=r"(r[3]) : "r"(a));
}
__device__ __forceinline__ void cpasync16(uint32_t saddr, const void* g) {
    asm volatile("cp.async.cg.shared.global [%0], [%1], 16;" :: "r"(saddr), "l"(g));
}
#define CP_COMMIT() asm volatile("cp.async.commit_group;" ::: "memory")
#define CP_WAIT1()  asm volatile("cp.async.wait_group 1;" ::: "memory")
#define CP_WAIT0()  asm volatile("cp.async.wait_group 0;" ::: "memory")

__device__ __forceinline__ void mma16n8k8(float c[4], const uint32_t a[4],
                                          const uint32_t b0, const uint32_t b1) {
    asm volatile(
        "mma.sync.aligned.m16n8k8.row.col.f32.tf32.tf32.f32 "
        "{%0,%1,%2,%3}, {%4,%5,%6,%7}, {%8,%9}, {%0,%1,%2,%3};"
        : "+f"(c[0]), "+f"(c[1]), "+f"(c[2]), "+f"(c[3])
        : "r"(a[0]), "r"(a[1]), "r"(a[2]), "r"(a[3]), "r"(b0), "r"(b1));
}
// exp(p) on [0,1]: degree-4 Chebyshev (max rel err ~1.8e-5), t = 2p-1
__device__ __forceinline__ float exp01(float p) {
    float t = fmaf(2.f, p, -1.f);
    float e = 0.00437510f;
    e = fmaf(e, t, 0.03501305f);
    e = fmaf(e, t, 0.20607264f);
    e = fmaf(e, t, 0.82412760f);
    e = fmaf(e, t, 1.64871112f);
    return e;
}

// ============================================================================
// tf32 pre-rounding: 7 tensors in one launch (z picks the tensor)
// ============================================================================
__global__ void round7_kernel(
    const float4* s0, float4* d0, int n0,
    const float4* s1, float4* d1, int n1,
    const float4* s2, float4* d2, int n2,
    const float4* s3, float4* d3, int n3,
    const float4* s4, float4* d4, int n4,
    const float4* s5, float4* d5, int n5,
    const float4* s6, float4* d6, int n6)
{
    const float4* s; float4* d; int n;
    switch (blockIdx.y) {
        case 0: s = s0; d = d0; n = n0; break;
        case 1: s = s1; d = d1; n = n1; break;
        case 2: s = s2; d = d2; n = n2; break;
        case 3: s = s3; d = d3; n = n3; break;
        case 4: s = s4; d = d4; n = n4; break;
        case 5: s = s5; d = d5; n = n5; break;
        default: s = s6; d = d6; n = n6; break;
    }
    for (int i = blockIdx.x * blockDim.x + threadIdx.x; i < n;
         i += gridDim.x * blockDim.x) {
        float4 v = __ldg(s + i);
        v.x = rnd_tf32(v.x); v.y = rnd_tf32(v.y);
        v.z = rnd_tf32(v.z); v.w = rnd_tf32(v.w);
        d[i] = v;
    }
}

// ============================================================================
// Projection GEMM: C = A @ W^T + bias (A, W already tf32-rounded in gmem).
// CTA 128x128, warp 32x64, BK=32, cp.async 2-stage, ldmatrix, 2 CTAs/SM.
// round_out: round C to tf32 (for attention consumers).
// vt_z: problem index written transposed as Vt[b][h][d][s] (-1 = none)
// ============================================================================
#define BM 128
#define BN 128
#define BKC 32
#define PAD 36
#define OFF_A0 0
#define OFF_B0 (BM*PAD)
#define OFF_A1 (OFF_B0 + BN*PAD)
#define OFF_B1 (OFF_A1 + BM*PAD)
#define SM_WORDS (OFF_B1 + BN*PAD)   // 18432 words = 73728 B
#define NCHUNK (EMB / BKC)

__global__ void __launch_bounds__(256, 2) gemm_tf32_mma(
    const float* __restrict__ A0, const float* __restrict__ W0, const float* __restrict__ b0_, float* __restrict__ C0,
    const float* __restrict__ A1, const float* __restrict__ W1, const float* __restrict__ b1_, float* __restrict__ C1,
    const float* __restrict__ A2, const float* __restrict__ W2, const float* __restrict__ b2_, float* __restrict__ C2,
    int vt_z, int round_out)
{
    extern __shared__ uint32_t sm[];
    const uint32_t sb = smem_u32(sm);

    const float* A    = blockIdx.z == 0 ? A0 : (blockIdx.z == 1 ? A1 : A2);
    const float* W    = blockIdx.z == 0 ? W0 : (blockIdx.z == 1 ? W1 : W2);
    const float* bias = blockIdx.z == 0 ? b0_ : (blockIdx.z == 1 ? b1_ : b2_);
    float*       C    = blockIdx.z == 0 ? C0 : (blockIdx.z == 1 ? C1 : C2);
    const bool tpose  = ((int)blockIdx.z == vt_z);

    const int tid  = threadIdx.x;
    const int lane = tid & 31;
    const int wid  = tid >> 5;
    const int wm   = wid >> 1;     // 0..3
    const int wn   = wid & 1;      // 0..1
    const int bm   = blockIdx.y * BM;
    const int bn   = blockIdx.x * BN;

    const float* Ap = A + (long)bm * EMB;
    const float* Wp = W + (long)bn * EMB;

    const int ld_r = tid >> 3;        // 0..31 (+32*i)
    const int ld_c = (tid & 7) * 4;   // float col within 32-wide chunk

    auto cpStage = [&](int c, int buf) {
        int k0 = c * BKC;
        uint32_t sA = sb + 4u * (buf ? OFF_A1 : OFF_A0);
        uint32_t sB = sb + 4u * (buf ? OFF_B1 : OFF_B0);
        #pragma unroll
        for (int i = 0; i < 4; i++) {
            int r = ld_r + i * 32;
            uint32_t so = 4u * (uint32_t)(r * PAD + ld_c);
            cpasync16(sA + so, Ap + (long)r * EMB + k0 + ld_c);
            cpasync16(sB + so, Wp + (long)r * EMB + k0 + ld_c);
        }
        CP_COMMIT();
    };

    float acc[2][8][4];
    #pragma unroll
    for (int mt = 0; mt < 2; mt++)
        #pragma unroll
        for (int nt = 0; nt < 8; nt++)
            #pragma unroll
            for (int j = 0; j < 4; j++) acc[mt][nt][j] = 0.f;

    cpStage(0, 0);
    cpStage(1, 1);

    // ldmatrix lane-address components (word offsets within tile)
    const int a_row = (lane & 7) + 8 * ((lane >> 3) & 1);
    const int a_kw  = 4 * (lane >> 4);
    const int b_row = (lane & 7) + 8 * (lane >> 4);
    const int b_kw  = 4 * ((lane >> 3) & 1);

    for (int c = 0; c < NCHUNK; c++) {
        if (c + 1 < NCHUNK) { CP_WAIT1(); } else { CP_WAIT0(); }
        __syncthreads();

        const uint32_t offA = (c & 1) ? OFF_A1 : OFF_A0;
        const uint32_t offB = (c & 1) ? OFF_B1 : OFF_B0;

        #pragma unroll
        for (int ks = 0; ks < 4; ks++) {
            uint32_t af[2][4], bf[8][2];
            #pragma unroll
            for (int mt = 0; mt < 2; mt++) {
                uint32_t addr = sb + 4u * (offA + (uint32_t)((wm * 32 + mt * 16 + a_row) * PAD + ks * 8 + a_kw));
                ldsm4(af[mt], addr);
            }
            #pragma unroll
            for (int g = 0; g < 4; g++) {
                uint32_t tmp[4];
                uint32_t addr = sb + 4u * (offB + (uint32_t)((wn * 64 + g * 16 + b_row) * PAD + ks * 8 + b_kw));
                ldsm4(tmp, addr);
                bf[2 * g][0] = tmp[0]; bf[2 * g][1] = tmp[1];
                bf[2 * g + 1][0] = tmp[2]; bf[2 * g + 1][1] = tmp[3];
            }
            #pragma unroll
            for (int mt = 0; mt < 2; mt++)
                #pragma unroll
                for (int nt = 0; nt < 8; nt++)
                    mma16n8k8(acc[mt][nt], af[mt], bf[nt][0], bf[nt][1]);
        }
        __syncthreads();
        if (c + 2 < NCHUNK) cpStage(c + 2, c & 1);
    }

    if (!tpose) {
        #pragma unroll
        for (int mt = 0; mt < 2; mt++) {
            int r0 = bm + wm * 32 + mt * 16 + (lane >> 2);
            #pragma unroll
            for (int nt = 0; nt < 8; nt++) {
                int col = bn + wn * 64 + nt * 8 + (lane & 3) * 2;
                float2 bb = *(const float2*)(bias + col);
                float2 o0, o1;
                o0.x = acc[mt][nt][0] + bb.x; o0.y = acc[mt][nt][1] + bb.y;
                o1.x = acc[mt][nt][2] + bb.x; o1.y = acc[mt][nt][3] + bb.y;
                if (round_out) {
                    o0.x = rnd_tf32(o0.x); o0.y = rnd_tf32(o0.y);
                    o1.x = rnd_tf32(o1.x); o1.y = rnd_tf32(o1.y);
                }
                *(float2*)(C + (long)r0 * EMB + col) = o0;
                *(float2*)(C + (long)(r0 + 8) * EMB + col) = o1;
            }
        }
    } else {
        #pragma unroll
        for (int mt = 0; mt < 2; mt++) {
            int r0 = bm + wm * 32 + mt * 16 + (lane >> 2);
            int b_ = r0 >> 11, s = r0 & (SEQ - 1);
            #pragma unroll
            for (int nt = 0; nt < 8; nt++) {
                int col = bn + wn * 64 + nt * 8 + (lane & 3) * 2;
                int h = col >> 6, d = col & 63;
                float2 bb = *(const float2*)(bias + col);
                float* base = C + ((long)((b_ * NH + h) * HD + d)) * SEQ + s;
                base[0]       = rnd_tf32(acc[mt][nt][0] + bb.x);
                base[SEQ]     = rnd_tf32(acc[mt][nt][1] + bb.y);
                base[8]       = rnd_tf32(acc[mt][nt][2] + bb.x);
                base[SEQ + 8] = rnd_tf32(acc[mt][nt][3] + bb.y);
            }
        }
    }
}

// ============================================================================
// Attention via mma.sync tf32 + ldmatrix + cp.async (operands pre-rounded).
// w = sigmoid(qk/8) in [0,1] -> exp(w) in [1,e]: single pass, no running max.
// CTA: 64 queries x one (b,h); 4 warps x 16 rows; 64-key tiles; 2 CTAs/SM.
// ============================================================================
#define AST 68
#define AOFF_K0 0
#define AOFF_K1 (64*AST)
#define AOFF_V0 (2*64*AST)
#define AOFF_V1 (3*64*AST)
#define AOFF_P  (4*64*AST)
#define A_WORDS (AOFF_P + 64*AST)   // 21760 words = 87040 B

__global__ void __launch_bounds__(128, 2) attn_mma(
    const float* __restrict__ Q, const float* __restrict__ K,
    const float* __restrict__ Vt, const int* __restrict__ indicator,
    float* __restrict__ O)
{
    extern __shared__ uint32_t sm[];
    const uint32_t sb = smem_u32(sm);
    const int tid  = threadIdx.x;
    const int lane = tid & 31;
    const int wid  = tid >> 5;             // 0..3
    const int b    = blockIdx.z;
    const int h    = blockIdx.y;
    const int q0   = blockIdx.x * 64;
    const int r    = lane >> 2;
    const int qq   = lane & 3;

    const float psign = __ldg(indicator) ? -0.5f : 0.5f;

    const int a_row = (lane & 7) + 8 * ((lane >> 3) & 1);
    const int a_kw  = 4 * (lane >> 4);
    const int b_row = (lane & 7) + 8 * (lane >> 4);
    const int b_kw  = 4 * ((lane >> 3) & 1);

    const int ld_rr = tid >> 4;        // 0..7 (+8*i)
    const int ld_cc = (tid & 15) * 4;  // float col

    // K/V cp.async stage (16 cp.async per thread per tile)
    auto cpKV = [&](int kt, int buf) {
        uint32_t pk0 = sb + 4u * (buf ? AOFF_K1 : AOFF_K0);
        uint32_t pv0 = sb + 4u * (buf ? AOFF_V1 : AOFF_V0);
        #pragma unroll
        for (int i = 0; i < 8; i++) {
            int rr = ld_rr + i * 8;
            uint32_t so = 4u * (uint32_t)(rr * AST + ld_cc);
            cpasync16(pk0 + so, K + ((long)(b * SEQ + kt + rr)) * EMB + h * HD + ld_cc);
            cpasync16(pv0 + so, Vt + ((long)((b * NH + h) * HD + rr)) * SEQ + kt + ld_cc);
        }
        CP_COMMIT();
    };

    // ---- stage Q tile [64][64] into P region (pre-rounded: raw copy)
    #pragma unroll
    for (int i = 0; i < 8; i++) {
        int idx = tid + i * 128;
        int rr = idx >> 4, cc = idx & 15;
        float4 v = __ldg((const float4*)(Q + ((long)(b * SEQ + q0 + rr)) * EMB + h * HD + cc * 4));
        *(float4*)(sm + AOFF_P + rr * AST + cc * 4) = v;
    }
    cpKV(0, 0);
    cpKV(64, 1);
    __syncthreads();

    uint32_t qf[8][4];
    #pragma unroll
    for (int ks = 0; ks < 8; ks++) {
        uint32_t addr = sb + 4u * (uint32_t)(AOFF_P + (wid * 16 + a_row) * AST + ks * 8 + a_kw);
        ldsm4(qf[ks], addr);
    }

    float oacc[8][4];
    #pragma unroll
    for (int nt = 0; nt < 8; nt++)
        #pragma unroll
        for (int j = 0; j < 4; j++) oacc[nt][j] = 0.f;
    float den0 = 0.f, den1 = 0.f;

    const int NT = SEQ / 64;
    for (int t = 0; t < NT; t++) {
        if (t + 1 < NT) { CP_WAIT1(); } else { CP_WAIT0(); }
        __syncthreads();

        const uint32_t offK = (t & 1) ? AOFF_K1 : AOFF_K0;
        const uint32_t offV = (t & 1) ? AOFF_V1 : AOFF_V0;

        // ---- S = Q @ K^T
        float sacc[8][4];
        #pragma unroll
        for (int nt = 0; nt < 8; nt++)
            #pragma unroll
            for (int j = 0; j < 4; j++) sacc[nt][j] = 0.f;

        #pragma unroll
        for (int ks = 0; ks < 8; ks++) {
            #pragma unroll
            for (int g = 0; g < 4; g++) {
                uint32_t bfr[4];
                uint32_t addr = sb + 4u * (offK + (uint32_t)((g * 16 + b_row) * AST + ks * 8 + b_kw));
                ldsm4(bfr, addr);
                mma16n8k8(sacc[2 * g],     qf[ks], bfr[0], bfr[1]);
                mma16n8k8(sacc[2 * g + 1], qf[ks], bfr[2], bfr[3]);
            }
        }

        // ---- p = exp01(sigmoid(s/8)); stage tf32(P)
        uint32_t* Ps = sm + AOFF_P + wid * 16 * AST;
        #pragma unroll
        for (int nt = 0; nt < 8; nt++) {
            float p0 = fmaf(psign, tanh_fast(sacc[nt][0] * 0.0625f), 0.5f);
            float p1 = fmaf(psign, tanh_fast(sacc[nt][1] * 0.0625f), 0.5f);
            float p2 = fmaf(psign, tanh_fast(sacc[nt][2] * 0.0625f), 0.5f);
            float p3 = fmaf(psign, tanh_fast(sacc[nt][3] * 0.0625f), 0.5f);
            p0 = exp01(p0); p1 = exp01(p1); p2 = exp01(p2); p3 = exp01(p3);
            den0 += p0 + p1;
            den1 += p2 + p3;
            uint32_t* ps = Ps + r * AST + nt * 8 + qq * 2;
            *(uint2*)ps = make_uint2(f2tf32(p0), f2tf32(p1));
            *(uint2*)(ps + 8 * AST) = make_uint2(f2tf32(p2), f2tf32(p3));
        }
        __syncwarp();

        // ---- O += P @ V
        #pragma unroll
        for (int ks = 0; ks < 8; ks++) {
            uint32_t af[4];
            uint32_t paddr = sb + 4u * (uint32_t)(AOFF_P + (wid * 16 + a_row) * AST + ks * 8 + a_kw);
            ldsm4(af, paddr);
            #pragma unroll
            for (int g = 0; g < 4; g++) {
                uint32_t bfr[4];
                uint32_t addr = sb + 4u * (offV + (uint32_t)((g * 16 + b_row) * AST + ks * 8 + b_kw));
                ldsm4(bfr, addr);
                mma16n8k8(oacc[2 * g],     af, bfr[0], bfr[1]);
                mma16n8k8(oacc[2 * g + 1], af, bfr[2], bfr[3]);
            }
        }
        __syncthreads();
        if (t + 2 < NT) cpKV((t + 2) * 64, t & 1);
    }

    den0 += __shfl_xor_sync(0xffffffffu, den0, 1);
    den0 += __shfl_xor_sync(0xffffffffu, den0, 2);
    den1 += __shfl_xor_sync(0xffffffffu, den1, 1);
    den1 += __shfl_xor_sync(0xffffffffu, den1, 2);
    float inv0 = 1.f / den0, inv1 = 1.f / den1;

    long row0 = (long)(b * SEQ + q0 + wid * 16 + r);
    #pragma unroll
    for (int nt = 0; nt < 8; nt++) {
        int col = h * HD + nt * 8 + qq * 2;
        float2 o0, o1;
        o0.x = rnd_tf32(oacc[nt][0] * inv0); o0.y = rnd_tf32(oacc[nt][1] * inv0);
        o1.x = rnd_tf32(oacc[nt][2] * inv1); o1.y = rnd_tf32(oacc[nt][3] * inv1);
        *(float2*)(O + row0 * EMB + col) = o0;
        *(float2*)(O + (row0 + 8) * EMB + col) = o1;
    }
}

// ----------------------------------------------------------------------------
extern "C" void kernel_launch(void* const* d_in, const int* in_sizes, int n_in,
                              void* d_out, int out_size)
{
    const float* queries = (const float*)d_in[0];
    const float* keys    = (const float*)d_in[1];
    const float* values  = (const float*)d_in[2];
    const float* Wq = (const float*)d_in[3];
    const float* bq = (const float*)d_in[4];
    const float* Wk = (const float*)d_in[5];
    const float* bk = (const float*)d_in[6];
    const float* Wv = (const float*)d_in[7];
    const float* bv = (const float*)d_in[8];
    const float* Wo = (const float*)d_in[9];
    const float* bo = (const float*)d_in[10];
    const int* indicator = (const int*)d_in[11];

    float *gq, *gk, *gvt, *ga, *gaq, *gak, *gav, *gwq, *gwk, *gwv, *gwo;
    cudaGetSymbolAddress((void**)&gq, g_q);
    cudaGetSymbolAddress((void**)&gk, g_k);
    cudaGetSymbolAddress((void**)&gvt, g_vt);
    cudaGetSymbolAddress((void**)&ga, g_attn);
    cudaGetSymbolAddress((void**)&gaq, g_aq);
    cudaGetSymbolAddress((void**)&gak, g_ak);
    cudaGetSymbolAddress((void**)&gav, g_av);
    cudaGetSymbolAddress((void**)&gwq, g_wq);
    cudaGetSymbolAddress((void**)&gwk, g_wk);
    cudaGetSymbolAddress((void**)&gwv, g_wv);
    cudaGetSymbolAddress((void**)&gwo, g_wo);

    static int attr_set = 0;
    if (!attr_set) {
        cudaFuncSetAttribute(gemm_tf32_mma,
                             cudaFuncAttributeMaxDynamicSharedMemorySize, SM_WORDS * 4);
        cudaFuncSetAttribute(attn_mma,
                             cudaFuncAttributeMaxDynamicSharedMemorySize, A_WORDS * 4);
        attr_set = 1;
    }

    const int NACT4 = MROWS * EMB / 4;   // 1048576
    const int NW4   = EMB * EMB / 4;     // 262144
    dim3 r7_grid(512, 7);
    round7_kernel<<<r7_grid, 256>>>(
        (const float4*)queries, (float4*)gaq, NACT4,
        (const float4*)keys,    (float4*)gak, NACT4,
        (const float4*)values,  (float4*)gav, NACT4,
        (const float4*)Wq, (float4*)gwq, NW4,
        (const float4*)Wk, (float4*)gwk, NW4,
        (const float4*)Wv, (float4*)gwv, NW4,
        (const float4*)Wo, (float4*)gwo, NW4);

    dim3 qkv_grid(EMB / BN, MROWS / BM, 3);   // 768 CTAs
    gemm_tf32_mma<<<qkv_grid, 256, SM_WORDS * 4>>>(
        gaq, gwq, bq, gq,
        gak, gwk, bk, gk,
        gav, gwv, bv, gvt,
        2 /* transpose z==2 (V) */, 1 /* round outputs */);

    dim3 attn_grid(SEQ / 64, NH, BS_);        // 1024 CTAs
    attn_mma<<<attn_grid, 128, A_WORDS * 4>>>(gq, gk, gvt, indicator, ga);

    dim3 o_grid(EMB / BN, MROWS / BM, 1);     // 256 CTAs
    gemm_tf32_mma<<<o_grid, 256, SM_WORDS * 4>>>(
        ga, gwo, bo, (float*)d_out,
        ga, gwo, bo, (float*)d_out,
        ga, gwo, bo, (float*)d_out,
        -1, 0);
}

// round 10
// speedup vs baseline: 8.9183x; 2.0062x over previous
#include <cuda_runtime.h>
#include <cuda_fp16.h>
#include <cstdint>

#define BS_  2
#define SEQ  2048
#define EMB  1024
#define NH   16
#define HD   64
#define MROWS (BS_*SEQ)   // 4096

// scratch (device globals) — fp16 pipeline
__device__ __half g_q[BS_*SEQ*EMB];
__device__ __half g_k[BS_*SEQ*EMB];
__device__ __half g_vt[BS_*NH*HD*SEQ];   // V transposed: [b][h][d][s]
__device__ __half g_attn[BS_*SEQ*EMB];
__device__ __half g_aq[BS_*SEQ*EMB];
__device__ __half g_ak[BS_*SEQ*EMB];
__device__ __half g_av[BS_*SEQ*EMB];
__device__ __half g_wq[EMB*EMB];
__device__ __half g_wk[EMB*EMB];
__device__ __half g_wv[EMB*EMB];
__device__ __half g_wo[EMB*EMB];

__device__ __forceinline__ uint32_t h2(float lo, float hi) {
    uint32_t r; asm("cvt.rn.f16x2.f32 %0, %1, %2;" : "=r"(r) : "f"(hi), "f"(lo));
    return r;
}
__device__ __forceinline__ float tanh_fast(float x) {
    float r; asm("tanh.approx.f32 %0, %1;" : "=f"(r) : "f"(x)); return r;
}
__device__ __forceinline__ uint32_t smem_u32(const void* p) {
    uint32_t a;
    asm("{ .reg .u64 t; cvta.to.shared.u64 t, %1; cvt.u32.u64 %0, t; }"
        : "=r"(a) : "l"(p));
    return a;
}
__device__ __forceinline__ void ldsm4(uint32_t r[4], uint32_t a) {
    asm volatile("ldmatrix.sync.aligned.m8n8.x4.shared.b16 {%0,%1,%2,%3}, [%4];"
        : "=r"(r[0]), "=r"(r[1]), "=r"(r[2]), "=r"(r[3]) : "r"(a));
}
__device__ __forceinline__ void cpasync16(uint32_t saddr, const void* g) {
    asm volatile("cp.async.cg.shared.global [%0], [%1], 16;" :: "r"(saddr), "l"(g));
}
#define CP_COMMIT() asm volatile("cp.async.commit_group;" ::: "memory")
#define CP_WAIT1()  asm volatile("cp.async.wait_group 1;" ::: "memory")
#define CP_WAIT0()  asm volatile("cp.async.wait_group 0;" ::: "memory")

__device__ __forceinline__ void mma_f16(float c[4], const uint32_t a[4],
                                        const uint32_t b0, const uint32_t b1) {
    asm volatile(
        "mma.sync.aligned.m16n8k16.row.col.f32.f16.f16.f32 "
        "{%0,%1,%2,%3}, {%4,%5,%6,%7}, {%8,%9}, {%0,%1,%2,%3};"
        : "+f"(c[0]), "+f"(c[1]), "+f"(c[2]), "+f"(c[3])
        : "r"(a[0]), "r"(a[1]), "r"(a[2]), "r"(a[3]), "r"(b0), "r"(b1));
}
// exp(p) on [0,1]: degree-4 Chebyshev (max rel err ~1.8e-5), t = 2p-1
__device__ __forceinline__ float exp01(float p) {
    float t = fmaf(2.f, p, -1.f);
    float e = 0.00437510f;
    e = fmaf(e, t, 0.03501305f);
    e = fmaf(e, t, 0.20607264f);
    e = fmaf(e, t, 0.82412760f);
    e = fmaf(e, t, 1.64871112f);
    return e;
}

// ============================================================================
// fp32 -> fp16 conversion of 7 tensors in one launch
// ============================================================================
__global__ void half7_kernel(
    const float4* s0, uint2* d0, int n0,
    const float4* s1, uint2* d1, int n1,
    const float4* s2, uint2* d2, int n2,
    const float4* s3, uint2* d3, int n3,
    const float4* s4, uint2* d4, int n4,
    const float4* s5, uint2* d5, int n5,
    const float4* s6, uint2* d6, int n6)
{
    const float4* s; uint2* d; int n;
    switch (blockIdx.y) {
        case 0: s = s0; d = d0; n = n0; break;
        case 1: s = s1; d = d1; n = n1; break;
        case 2: s = s2; d = d2; n = n2; break;
        case 3: s = s3; d = d3; n = n3; break;
        case 4: s = s4; d = d4; n = n4; break;
        case 5: s = s5; d = d5; n = n5; break;
        default: s = s6; d = d6; n = n6; break;
    }
    for (int i = blockIdx.x * blockDim.x + threadIdx.x; i < n;
         i += gridDim.x * blockDim.x) {
        float4 v = __ldg(s + i);
        d[i] = make_uint2(h2(v.x, v.y), h2(v.z, v.w));
    }
}

// ============================================================================
// Projection GEMM (fp16 mma, f32 acc): C = A @ W^T + bias.
// CTA 128x128, warp 32x64, K-chunk 64 halves (4 k16 steps), 3-stage cp.async,
// ONE sync per chunk, ldmatrix, 2 CTAs/SM.
// mode per z: 0 = fp32 out, 1 = half out, 2 = half transposed Vt[b][h][d][s]
// ============================================================================
#define GST 144                 // smem row stride bytes (72 halves)
#define G_ATILE (128*GST)       // 18432 B
#define G_STAGE (2*G_ATILE)     // A+B per stage = 36864 B
#define G_SMEM  (3*G_STAGE)     // 110592 B
#define GBK 64                  // K-chunk (halves)
#define GNCHUNK (EMB/GBK)       // 16

__global__ void __launch_bounds__(256, 2) gemm_f16(
    const __half* __restrict__ A0, const __half* __restrict__ W0, const float* __restrict__ b0_, void* __restrict__ C0,
    const __half* __restrict__ A1, const __half* __restrict__ W1, const float* __restrict__ b1_, void* __restrict__ C1,
    const __half* __restrict__ A2, const __half* __restrict__ W2, const float* __restrict__ b2_, void* __restrict__ C2,
    int mode0, int mode1, int mode2)
{
    extern __shared__ char smc[];
    const uint32_t sb = smem_u32(smc);

    const __half* A    = blockIdx.z == 0 ? A0 : (blockIdx.z == 1 ? A1 : A2);
    const __half* W    = blockIdx.z == 0 ? W0 : (blockIdx.z == 1 ? W1 : W2);
    const float*  bias = blockIdx.z == 0 ? b0_ : (blockIdx.z == 1 ? b1_ : b2_);
    void*         C    = blockIdx.z == 0 ? C0 : (blockIdx.z == 1 ? C1 : C2);
    const int     mode = blockIdx.z == 0 ? mode0 : (blockIdx.z == 1 ? mode1 : mode2);

    const int tid  = threadIdx.x;
    const int lane = tid & 31;
    const int wid  = tid >> 5;
    const int wm   = wid >> 1;     // 0..3
    const int wn   = wid & 1;      // 0..1
    const int bm   = blockIdx.y * 128;
    const int bn   = blockIdx.x * 128;

    const __half* Ap = A + (long)bm * EMB;
    const __half* Wp = W + (long)bn * EMB;

    // cp.async: per stage, A: 128 rows x 8 chunks(16B) = 1024; same for B.
    auto cpStage = [&](int c, int s) {
        int k0 = c * GBK;
        uint32_t sA = sb + (uint32_t)(s * G_STAGE);
        uint32_t sB = sA + G_ATILE;
        #pragma unroll
        for (int i = 0; i < 4; i++) {
            int id = tid + i * 256;
            int r = id >> 3, c8 = id & 7;
            uint32_t so = (uint32_t)(r * GST + c8 * 16);
            cpasync16(sA + so, Ap + (long)r * EMB + k0 + c8 * 8);
            cpasync16(sB + so, Wp + (long)r * EMB + k0 + c8 * 8);
        }
        CP_COMMIT();
    };

    float acc[2][8][4];
    #pragma unroll
    for (int mt = 0; mt < 2; mt++)
        #pragma unroll
        for (int nt = 0; nt < 8; nt++)
            #pragma unroll
            for (int j = 0; j < 4; j++) acc[mt][nt][j] = 0.f;

    cpStage(0, 0);
    cpStage(1, 1);

    // ldmatrix lane mappings (fp16 k16 fragments)
    const int a_row = lane & 15;                 // + mt*16 + wm*32
    const int a_kb  = (lane >> 4) * 16;          // byte k-offset within k16
    const int b_row = (lane & 7) + 8 * (lane >> 4);
    const int b_kb  = ((lane >> 3) & 1) * 16;

    for (int c = 0; c < GNCHUNK; c++) {
        if (c + 2 < GNCHUNK) { CP_WAIT1(); } else { CP_WAIT0(); }
        __syncthreads();
        if (c + 2 < GNCHUNK) cpStage(c + 2, (c + 2) % 3);

        const uint32_t st = sb + (uint32_t)((c % 3) * G_STAGE);

        #pragma unroll
        for (int ks = 0; ks < 4; ks++) {
            uint32_t af[2][4], bf[8][2];
            #pragma unroll
            for (int mt = 0; mt < 2; mt++) {
                uint32_t addr = st + (uint32_t)((wm * 32 + mt * 16 + a_row) * GST + ks * 32 + a_kb);
                ldsm4(af[mt], addr);
            }
            #pragma unroll
            for (int g = 0; g < 4; g++) {
                uint32_t tmp[4];
                uint32_t addr = st + (uint32_t)(G_ATILE + (wn * 64 + g * 16 + b_row) * GST + ks * 32 + b_kb);
                ldsm4(tmp, addr);
                bf[2 * g][0] = tmp[0]; bf[2 * g][1] = tmp[1];
                bf[2 * g + 1][0] = tmp[2]; bf[2 * g + 1][1] = tmp[3];
            }
            #pragma unroll
            for (int mt = 0; mt < 2; mt++)
                #pragma unroll
                for (int nt = 0; nt < 8; nt++)
                    mma_f16(acc[mt][nt], af[mt], bf[nt][0], bf[nt][1]);
        }
        __syncthreads();
    }

    if (mode == 0) {
        float* Cf = (float*)C;
        #pragma unroll
        for (int mt = 0; mt < 2; mt++) {
            int r0 = bm + wm * 32 + mt * 16 + (lane >> 2);
            #pragma unroll
            for (int nt = 0; nt < 8; nt++) {
                int col = bn + wn * 64 + nt * 8 + (lane & 3) * 2;
                float2 bb = *(const float2*)(bias + col);
                float2 o0, o1;
                o0.x = acc[mt][nt][0] + bb.x; o0.y = acc[mt][nt][1] + bb.y;
                o1.x = acc[mt][nt][2] + bb.x; o1.y = acc[mt][nt][3] + bb.y;
                *(float2*)(Cf + (long)r0 * EMB + col) = o0;
                *(float2*)(Cf + (long)(r0 + 8) * EMB + col) = o1;
            }
        }
    } else if (mode == 1) {
        __half* Ch = (__half*)C;
        #pragma unroll
        for (int mt = 0; mt < 2; mt++) {
            int r0 = bm + wm * 32 + mt * 16 + (lane >> 2);
            #pragma unroll
            for (int nt = 0; nt < 8; nt++) {
                int col = bn + wn * 64 + nt * 8 + (lane & 3) * 2;
                float2 bb = *(const float2*)(bias + col);
                uint32_t w0 = h2(acc[mt][nt][0] + bb.x, acc[mt][nt][1] + bb.y);
                uint32_t w1 = h2(acc[mt][nt][2] + bb.x, acc[mt][nt][3] + bb.y);
                *(uint32_t*)(Ch + (long)r0 * EMB + col) = w0;
                *(uint32_t*)(Ch + (long)(r0 + 8) * EMB + col) = w1;
            }
        }
    } else {
        // transposed half: Vt[((b*NH+h)*HD + d)*SEQ + s]
        __half* Ch = (__half*)C;
        #pragma unroll
        for (int mt = 0; mt < 2; mt++) {
            int r0 = bm + wm * 32 + mt * 16 + (lane >> 2);
            int b_ = r0 >> 11, s = r0 & (SEQ - 1);
            #pragma unroll
            for (int nt = 0; nt < 8; nt++) {
                int col = bn + wn * 64 + nt * 8 + (lane & 3) * 2;
                int h = col >> 6, d = col & 63;
                float2 bb = *(const float2*)(bias + col);
                __half* base = Ch + ((long)((b_ * NH + h) * HD + d)) * SEQ + s;
                base[0]       = __float2half_rn(acc[mt][nt][0] + bb.x);
                base[SEQ]     = __float2half_rn(acc[mt][nt][1] + bb.y);
                base[8]       = __float2half_rn(acc[mt][nt][2] + bb.x);
                base[SEQ + 8] = __float2half_rn(acc[mt][nt][3] + bb.y);
            }
        }
    }
}

// ============================================================================
// Attention (fp16 mma, f32 acc): w = sigmoid(qk/8) in [0,1] -> exp in [1,e],
// single pass, no running max.  CTA: 64 queries x one (b,h); 4 warps.
// 64-key tiles, 3-stage cp.async (1 sync/tile), P repacked in REGISTERS.
// smem: stages s at s*18432 (K 9216 + V 9216), Q at 55296. Total 64512 B.
// ============================================================================
#define A_KTILE 9216
#define A_STAGE 18432
#define A_QOFF  55296
#define A_BYTES 64512

__global__ void __launch_bounds__(128, 2) attn_f16(
    const __half* __restrict__ Q, const __half* __restrict__ K,
    const __half* __restrict__ Vt, const int* __restrict__ indicator,
    __half* __restrict__ O)
{
    extern __shared__ char smc[];
    const uint32_t sb = smem_u32(smc);
    const int tid  = threadIdx.x;
    const int lane = tid & 31;
    const int wid  = tid >> 5;             // 0..3
    const int b    = blockIdx.z;
    const int h    = blockIdx.y;
    const int q0   = blockIdx.x * 64;
    const int r    = lane >> 2;
    const int qq   = lane & 3;

    const float psign = __ldg(indicator) ? -0.5f : 0.5f;

    const int a_row = lane & 15;
    const int a_kb  = (lane >> 4) * 16;
    const int b_row = (lane & 7) + 8 * (lane >> 4);
    const int b_kb  = ((lane >> 3) & 1) * 16;

    // K/V cp.async: per tile K 64 rows x 8 chunks + V same = 1024 cp /128 thr
    auto cpKV = [&](int kt, int s) {
        uint32_t pk = sb + (uint32_t)(s * A_STAGE);
        uint32_t pv = pk + A_KTILE;
        #pragma unroll
        for (int i = 0; i < 4; i++) {
            int id = tid + i * 128;
            int rr = id >> 3, c8 = id & 7;
            uint32_t so = (uint32_t)(rr * GST + c8 * 16);
            cpasync16(pk + so, K + ((long)(b * SEQ + kt + rr)) * EMB + h * HD + c8 * 8);
            cpasync16(pv + so, Vt + ((long)((b * NH + h) * HD + rr)) * SEQ + kt + c8 * 8);
        }
        CP_COMMIT();
    };

    cpKV(0, 0);
    cpKV(64, 1);

    // stage Q tile [64 rows][64 halves] (raw 16B copies; already fp16)
    #pragma unroll
    for (int i = 0; i < 4; i++) {
        int id = tid + i * 128;
        int rr = id >> 3, c8 = id & 7;
        uint4 v = *(const uint4*)(Q + ((long)(b * SEQ + q0 + rr)) * EMB + h * HD + c8 * 8);
        *(uint4*)(smc + A_QOFF + rr * GST + c8 * 16) = v;
    }
    __syncthreads();

    uint32_t qf[4][4];
    #pragma unroll
    for (int ks = 0; ks < 4; ks++) {
        uint32_t addr = sb + (uint32_t)(A_QOFF + (wid * 16 + a_row) * GST + ks * 32 + a_kb);
        ldsm4(qf[ks], addr);
    }

    float oacc[8][4];
    #pragma unroll
    for (int nt = 0; nt < 8; nt++)
        #pragma unroll
        for (int j = 0; j < 4; j++) oacc[nt][j] = 0.f;
    float den0 = 0.f, den1 = 0.f;

    const int NT = SEQ / 64;
    for (int t = 0; t < NT; t++) {
        if (t + 2 < NT) { CP_WAIT1(); } else { CP_WAIT0(); }
        __syncthreads();
        if (t + 2 < NT) cpKV((t + 2) * 64, (t + 2) % 3);

        const uint32_t stK = sb + (uint32_t)((t % 3) * A_STAGE);
        const uint32_t stV = stK + A_KTILE;

        // ---- S = Q @ K^T  (warp: 16 rows x 64 keys)
        float sacc[8][4];
        #pragma unroll
        for (int nt = 0; nt < 8; nt++)
            #pragma unroll
            for (int j = 0; j < 4; j++) sacc[nt][j] = 0.f;

        #pragma unroll
        for (int ks = 0; ks < 4; ks++) {
            #pragma unroll
            for (int g = 0; g < 4; g++) {
                uint32_t tmp[4];
                uint32_t addr = stK + (uint32_t)((g * 16 + b_row) * GST + ks * 32 + b_kb);
                ldsm4(tmp, addr);
                mma_f16(sacc[2 * g],     qf[ks], tmp[0], tmp[1]);
                mma_f16(sacc[2 * g + 1], qf[ks], tmp[2], tmp[3]);
            }
        }

        // ---- p = exp01(sigmoid(s/8)); pack fp16 A-frags in registers
        uint32_t pw[8][2];
        #pragma unroll
        for (int nt = 0; nt < 8; nt++) {
            float p0 = fmaf(psign, tanh_fast(sacc[nt][0] * 0.0625f), 0.5f);
            float p1 = fmaf(psign, tanh_fast(sacc[nt][1] * 0.0625f), 0.5f);
            float p2 = fmaf(psign, tanh_fast(sacc[nt][2] * 0.0625f), 0.5f);
            float p3 = fmaf(psign, tanh_fast(sacc[nt][3] * 0.0625f), 0.5f);
            p0 = exp01(p0); p1 = exp01(p1); p2 = exp01(p2); p3 = exp01(p3);
            den0 += p0 + p1;
            den1 += p2 + p3;
            pw[nt][0] = h2(p0, p1);     // row r,   keys (2qq, 2qq+1)
            pw[nt][1] = h2(p2, p3);     // row r+8
        }

        // ---- O += P @ V  (P from registers; V B-frags via ldmatrix)
        #pragma unroll
        for (int ks = 0; ks < 4; ks++) {
            uint32_t af[4] = { pw[2 * ks][0], pw[2 * ks][1],
                               pw[2 * ks + 1][0], pw[2 * ks + 1][1] };
            #pragma unroll
            for (int g = 0; g < 4; g++) {
                uint32_t tmp[4];
                uint32_t addr = stV + (uint32_t)((g * 16 + b_row) * GST + ks * 32 + b_kb);
                ldsm4(tmp, addr);
                mma_f16(oacc[2 * g],     af, tmp[0], tmp[1]);
                mma_f16(oacc[2 * g + 1], af, tmp[2], tmp[3]);
            }
        }
    }

    den0 += __shfl_xor_sync(0xffffffffu, den0, 1);
    den0 += __shfl_xor_sync(0xffffffffu, den0, 2);
    den1 += __shfl_xor_sync(0xffffffffu, den1, 1);
    den1 += __shfl_xor_sync(0xffffffffu, den1, 2);
    float inv0 = 1.f / den0, inv1 = 1.f / den1;

    long row0 = (long)(b * SEQ + q0 + wid * 16 + r);
    #pragma unroll
    for (int nt = 0; nt < 8; nt++) {
        int col = h * HD + nt * 8 + qq * 2;
        uint32_t w0 = h2(oacc[nt][0] * inv0, oacc[nt][1] * inv0);
        uint32_t w1 = h2(oacc[nt][2] * inv1, oacc[nt][3] * inv1);
        *(uint32_t*)(O + row0 * EMB + col) = w0;
        *(uint32_t*)(O + (row0 + 8) * EMB + col) = w1;
    }
}

// ----------------------------------------------------------------------------
extern "C" void kernel_launch(void* const* d_in, const int* in_sizes, int n_in,
                              void* d_out, int out_size)
{
    const float* queries = (const float*)d_in[0];
    const float* keys    = (const float*)d_in[1];
    const float* values  = (const float*)d_in[2];
    const float* Wq = (const float*)d_in[3];
    const float* bq = (const float*)d_in[4];
    const float* Wk = (const float*)d_in[5];
    const float* bk = (const float*)d_in[6];
    const float* Wv = (const float*)d_in[7];
    const float* bv = (const float*)d_in[8];
    const float* Wo = (const float*)d_in[9];
    const float* bo = (const float*)d_in[10];
    const int* indicator = (const int*)d_in[11];

    __half *gq, *gk, *gvt, *ga, *gaq, *gak, *gav, *gwq, *gwk, *gwv, *gwo;
    cudaGetSymbolAddress((void**)&gq, g_q);
    cudaGetSymbolAddress((void**)&gk, g_k);
    cudaGetSymbolAddress((void**)&gvt, g_vt);
    cudaGetSymbolAddress((void**)&ga, g_attn);
    cudaGetSymbolAddress((void**)&gaq, g_aq);
    cudaGetSymbolAddress((void**)&gak, g_ak);
    cudaGetSymbolAddress((void**)&gav, g_av);
    cudaGetSymbolAddress((void**)&gwq, g_wq);
    cudaGetSymbolAddress((void**)&gwk, g_wk);
    cudaGetSymbolAddress((void**)&gwv, g_wv);
    cudaGetSymbolAddress((void**)&gwo, g_wo);

    static int attr_set = 0;
    if (!attr_set) {
        cudaFuncSetAttribute(gemm_f16,
                             cudaFuncAttributeMaxDynamicSharedMemorySize, G_SMEM);
        cudaFuncSetAttribute(attn_f16,
                             cudaFuncAttributeMaxDynamicSharedMemorySize, A_BYTES);
        attr_set = 1;
    }

    const int NACT4 = MROWS * EMB / 4;   // 1048576
    const int NW4   = EMB * EMB / 4;     // 262144
    dim3 h7_grid(512, 7);
    half7_kernel<<<h7_grid, 256>>>(
        (const float4*)queries, (uint2*)gaq, NACT4,
        (const float4*)keys,    (uint2*)gak, NACT4,
        (const float4*)values,  (uint2*)gav, NACT4,
        (const float4*)Wq, (uint2*)gwq, NW4,
        (const float4*)Wk, (uint2*)gwk, NW4,
        (const float4*)Wv, (uint2*)gwv, NW4,
        (const float4*)Wo, (uint2*)gwo, NW4);

    dim3 qkv_grid(EMB / 128, MROWS / 128, 3);   // 768 CTAs
    gemm_f16<<<qkv_grid, 256, G_SMEM>>>(
        gaq, gwq, bq, (void*)gq,
        gak, gwk, bk, (void*)gk,
        gav, gwv, bv, (void*)gvt,
        1, 1, 2);

    dim3 attn_grid(SEQ / 64, NH, BS_);          // 1024 CTAs
    attn_f16<<<attn_grid, 128, A_BYTES>>>(gq, gk, gvt, indicator, ga);

    dim3 o_grid(EMB / 128, MROWS / 128, 1);     // 256 CTAs
    gemm_f16<<<o_grid, 256, G_SMEM>>>(
        ga, gwo, bo, d_out,
        ga, gwo, bo, d_out,
        ga, gwo, bo, d_out,
        0, 0, 0);
}